// round 1
// baseline (speedup 1.0000x reference)
#include <cuda_runtime.h>
#include <math.h>
#include <float.h>

#define NPTS   1024
#define BATCH  4
#define TOTAL  (BATCH*NPTS)      // 4096
#define DCH    128
#define KMAX   100

// ---------------- scratch (static device globals; no allocation) ----------------
__device__ int   g_nbr[TOTAL*KMAX];          // sorted 100-NN per point
__device__ float g_raw[6][TOTAL*DCH];        // raw (pre-BN) features per stage
__device__ float g_fo[TOTAL*256];            // fm@W + bias buffer (reused)
__device__ float g_scale[6*DCH];             // BN fused scale per stage
__device__ float g_shift[6*DCH];             // BN fused shift per stage

// ---------------- KNN: one block (128 thr) per point, sorted top-101 -----------
__global__ void knn_kernel(const float* __restrict__ verts, int* __restrict__ nbr)
{
    int p = blockIdx.x;
    int b = p >> 10, i = p & (NPTS-1);
    const float* vb = verts + b*NPTS*3;
    int tid = threadIdx.x;

    float xi = vb[i*3+0], yi = vb[i*3+1], zi = vb[i*3+2];
    float sqi = xi*xi + yi*yi + zi*zi;

    float d[8];
#pragma unroll
    for (int s = 0; s < 8; s++) {
        int j = tid + s*128;
        float xj = vb[j*3+0], yj = vb[j*3+1], zj = vb[j*3+2];
        float sqj = xj*xj + yj*yj + zj*zj;
        float dot = xi*xj + yi*yj + zi*zj;
        d[s] = sqi + sqj - 2.0f*dot;       // same formula as reference
    }

    // local best (smallest d, ties -> smallest index: scan in increasing j)
    float bv = FLT_MAX; int bix = 0x7fffffff;
#pragma unroll
    for (int s = 0; s < 8; s++) {
        int j = tid + s*128;
        if (d[s] < bv) { bv = d[s]; bix = j; }
    }

    __shared__ float swv[4];
    __shared__ int   swi[4];
    __shared__ int   winner;
    int lane = tid & 31, warp = tid >> 5;

    for (int t = 0; t <= KMAX; t++) {      // 101 picks; pick 0 is self -> dropped
        float v = bv; int ix = bix;
#pragma unroll
        for (int off = 16; off; off >>= 1) {
            float v2 = __shfl_xor_sync(0xffffffffu, v, off);
            int   i2 = __shfl_xor_sync(0xffffffffu, ix, off);
            if (v2 < v || (v2 == v && i2 < ix)) { v = v2; ix = i2; }
        }
        if (lane == 0) { swv[warp] = v; swi[warp] = ix; }
        __syncthreads();
        if (tid == 0) {
            float v0 = swv[0]; int i0 = swi[0];
#pragma unroll
            for (int w = 1; w < 4; w++)
                if (swv[w] < v0 || (swv[w] == v0 && swi[w] < i0)) { v0 = swv[w]; i0 = swi[w]; }
            winner = i0;
            if (t > 0) nbr[p*KMAX + (t-1)] = i0;
        }
        __syncthreads();
        int w = winner;
        if ((w & 127) == tid) {
            d[w >> 7] = FLT_MAX;
            bv = FLT_MAX; bix = 0x7fffffff;
#pragma unroll
            for (int s = 0; s < 8; s++) {
                int j = tid + s*128;
                if (d[s] < bv) { bv = d[s]; bix = j; }
            }
        }
    }
}

// ---------------- conv kernels: warp per point, lane owns 4 channels -----------
template<bool LAYER>
__global__ void conv_kernel(const float* __restrict__ verts, const int* __restrict__ nbr,
                            const float* __restrict__ dirs, const float* __restrict__ fo,
                            float* __restrict__ raw, int K)
{
    int lane = threadIdx.x & 31, warp = threadIdx.x >> 5;
    int p = blockIdx.x*8 + warp;
    int b = p >> 10, i = p & (NPTS-1);

    // normalized directions (per column) held in registers
    float dn0[4], dn1[4], dn2[4];
#pragma unroll
    for (int c = 0; c < 4; c++) {
        int col = lane + 32*c;
        float a0 = dirs[col], a1 = dirs[128+col], a2 = dirs[256+col];
        float inv = 1.0f / fmaxf(sqrtf(a0*a0 + a1*a1 + a2*a2), 1e-12f);
        dn0[c] = a0*inv; dn1[c] = a1*inv; dn2[c] = a2*inv;
    }

    const float* vb = verts + b*NPTS*3;
    float xi = vb[i*3+0], yi = vb[i*3+1], zi = vb[i*3+2];

    float acc[4] = {-FLT_MAX, -FLT_MAX, -FLT_MAX, -FLT_MAX};
    const int* nb = nbr + p*KMAX;

#pragma unroll 2
    for (int kk = 0; kk < K; kk++) {
        int j = nb[kk];
        float dx = vb[j*3+0] - xi, dy = vb[j*3+1] - yi, dz = vb[j*3+2] - zi;
        float inv = 1.0f / fmaxf(sqrtf(dx*dx + dy*dy + dz*dz), 1e-12f);
        float nx = dx*inv, ny = dy*inv, nz = dz*inv;
        const float* fsrow = LAYER ? (fo + (size_t)(b*NPTS + j)*256 + 128) : (const float*)0;
#pragma unroll
        for (int c = 0; c < 4; c++) {
            float th = fmaxf(nx*dn0[c] + ny*dn1[c] + nz*dn2[c], 0.0f);
            if (LAYER) {
                float fs = fsrow[lane + 32*c];
                acc[c] = fmaxf(acc[c], th*fs);
            } else {
                acc[c] = fmaxf(acc[c], th);
            }
        }
    }

#pragma unroll
    for (int c = 0; c < 4; c++) {
        float o = acc[c];
        if (LAYER) o += fo[(size_t)p*256 + lane + 32*c];   // fc term
        raw[p*DCH + lane + 32*c] = o;
    }
}

// ---------------- BN stats: block per channel, emits fused scale/shift ---------
__global__ void stats_kernel(const float* __restrict__ raw, const float* __restrict__ g,
                             const float* __restrict__ be, float* __restrict__ scale,
                             float* __restrict__ shift)
{
    int c = blockIdx.x, tid = threadIdx.x;
    float s = 0.f, s2 = 0.f;
    for (int r = tid; r < TOTAL; r += 256) {
        float x = raw[r*DCH + c];
        s += x; s2 += x*x;
    }
    __shared__ float sh_s[256], sh_s2[256];
    sh_s[tid] = s; sh_s2[tid] = s2;
    __syncthreads();
    for (int off = 128; off; off >>= 1) {
        if (tid < off) { sh_s[tid] += sh_s[tid+off]; sh_s2[tid] += sh_s2[tid+off]; }
        __syncthreads();
    }
    if (tid == 0) {
        float mean = sh_s[0] * (1.0f/TOTAL);
        float var  = fmaxf(sh_s2[0] * (1.0f/TOTAL) - mean*mean, 0.f);
        float sc   = g[c] * rsqrtf(var + 1e-5f);
        scale[c] = sc;
        shift[c] = be[c] - mean*sc;
    }
}

// ---------------- fo = bn_relu(raw) @ W + bias  (4096x128 @ 128x256) -----------
__global__ void fo_kernel(const float* __restrict__ raw, const float* __restrict__ scale,
                          const float* __restrict__ shift, const float* __restrict__ W,
                          const float* __restrict__ bias, float* __restrict__ fo)
{
    __shared__ float in_s[32*128];
    int tid = threadIdx.x;
    int r0 = blockIdx.x*32;
    for (int idx = tid; idx < 32*128; idx += 256) {
        int r = idx >> 7, c = idx & 127;
        float x = raw[(r0+r)*DCH + c];
        in_s[idx] = fmaxf(fmaf(x, scale[c], shift[c]), 0.f);
    }
    __syncthreads();

    float acc[32];
#pragma unroll
    for (int r = 0; r < 32; r++) acc[r] = 0.f;

    for (int k = 0; k < 128; k += 4) {
        float w0 = W[(k+0)*256 + tid];
        float w1 = W[(k+1)*256 + tid];
        float w2 = W[(k+2)*256 + tid];
        float w3 = W[(k+3)*256 + tid];
#pragma unroll
        for (int r = 0; r < 32; r++) {
            float4 v = *(const float4*)&in_s[r*128 + k];
            acc[r] = fmaf(v.x, w0, acc[r]);
            acc[r] = fmaf(v.y, w1, acc[r]);
            acc[r] = fmaf(v.z, w2, acc[r]);
            acc[r] = fmaf(v.w, w3, acc[r]);
        }
    }
    float bb = bias[tid];
#pragma unroll
    for (int r = 0; r < 32; r++)
        fo[(size_t)(r0+r)*256 + tid] = acc[r] + bb;
}

// ---------------- final: relu( concat(bn_relu x3) @ W_down + b_down ) ----------
__global__ void final_kernel(const float* __restrict__ rl, const float* __restrict__ scl, const float* __restrict__ shl,
                             const float* __restrict__ rm, const float* __restrict__ scm, const float* __restrict__ shm,
                             const float* __restrict__ rg, const float* __restrict__ scg, const float* __restrict__ shg,
                             const float* __restrict__ Wd, const float* __restrict__ bd,
                             float* __restrict__ out)
{
    __shared__ float in_s[32*384];   // 48KB
    int tid = threadIdx.x;
    int r0 = blockIdx.x*32;
    for (int idx = tid; idx < 32*384; idx += 256) {
        int r = idx / 384;
        int c = idx - r*384;
        const float* raw; const float* sc; const float* sh; int cc;
        if (c < 128)      { raw = rl; sc = scl; sh = shl; cc = c; }
        else if (c < 256) { raw = rm; sc = scm; sh = shm; cc = c-128; }
        else              { raw = rg; sc = scg; sh = shg; cc = c-256; }
        float x = raw[(r0+r)*DCH + cc];
        in_s[idx] = fmaxf(fmaf(x, sc[cc], sh[cc]), 0.f);
    }
    __syncthreads();

    float acc[32];
#pragma unroll
    for (int r = 0; r < 32; r++) acc[r] = 0.f;

    for (int k = 0; k < 384; k += 4) {
        float w0 = Wd[(k+0)*256 + tid];
        float w1 = Wd[(k+1)*256 + tid];
        float w2 = Wd[(k+2)*256 + tid];
        float w3 = Wd[(k+3)*256 + tid];
#pragma unroll
        for (int r = 0; r < 32; r++) {
            float4 v = *(const float4*)&in_s[r*384 + k];
            acc[r] = fmaf(v.x, w0, acc[r]);
            acc[r] = fmaf(v.y, w1, acc[r]);
            acc[r] = fmaf(v.z, w2, acc[r]);
            acc[r] = fmaf(v.w, w3, acc[r]);
        }
    }
    float bb = bd[tid];
#pragma unroll
    for (int r = 0; r < 32; r++)
        out[(size_t)(r0+r)*256 + tid] = fmaxf(acc[r] + bb, 0.f);
}

// ---------------- launcher ------------------------------------------------------
extern "C" void kernel_launch(void* const* d_in, const int* in_sizes, int n_in,
                              void* d_out, int out_size)
{
    const float* verts   = (const float*)d_in[0];
    const float* dirs_l  = (const float*)d_in[1];
    const float* dirs_m0 = (const float*)d_in[2];
    const float* W_m1    = (const float*)d_in[3];
    const float* b_m1    = (const float*)d_in[4];
    const float* dirs_m1 = (const float*)d_in[5];
    const float* dirs_g0 = (const float*)d_in[6];
    const float* W_g1    = (const float*)d_in[7];
    const float* b_g1    = (const float*)d_in[8];
    const float* dirs_g1 = (const float*)d_in[9];
    const float* W_g2    = (const float*)d_in[10];
    const float* b_g2    = (const float*)d_in[11];
    const float* dirs_g2 = (const float*)d_in[12];
    const float* g_l   = (const float*)d_in[13];
    const float* be_l  = (const float*)d_in[14];
    const float* g_m0  = (const float*)d_in[15];
    const float* be_m0 = (const float*)d_in[16];
    const float* g_m1  = (const float*)d_in[17];
    const float* be_m1 = (const float*)d_in[18];
    const float* g_g0  = (const float*)d_in[19];
    const float* be_g0 = (const float*)d_in[20];
    const float* g_g1  = (const float*)d_in[21];
    const float* be_g1 = (const float*)d_in[22];
    const float* g_g2  = (const float*)d_in[23];
    const float* be_g2 = (const float*)d_in[24];
    const float* W_down = (const float*)d_in[25];
    const float* b_down = (const float*)d_in[26];
    float* out = (float*)d_out;

    int*   nbr;   cudaGetSymbolAddress((void**)&nbr,   g_nbr);
    float* raw;   cudaGetSymbolAddress((void**)&raw,   g_raw);
    float* fo;    cudaGetSymbolAddress((void**)&fo,    g_fo);
    float* scale; cudaGetSymbolAddress((void**)&scale, g_scale);
    float* shift; cudaGetSymbolAddress((void**)&shift, g_shift);

#define RAW(s) (raw + (size_t)(s)*TOTAL*DCH)

    knn_kernel<<<TOTAL, 128>>>(verts, nbr);

    // local branch (k=5)
    conv_kernel<false><<<TOTAL/8, 256>>>(verts, nbr, dirs_l, 0, RAW(0), 5);
    stats_kernel<<<DCH, 256>>>(RAW(0), g_l, be_l, scale+0*DCH, shift+0*DCH);

    // medium branch (k=20)
    conv_kernel<false><<<TOTAL/8, 256>>>(verts, nbr, dirs_m0, 0, RAW(1), 20);
    stats_kernel<<<DCH, 256>>>(RAW(1), g_m0, be_m0, scale+1*DCH, shift+1*DCH);
    fo_kernel<<<TOTAL/32, 256>>>(RAW(1), scale+1*DCH, shift+1*DCH, W_m1, b_m1, fo);
    conv_kernel<true><<<TOTAL/8, 256>>>(verts, nbr, dirs_m1, fo, RAW(2), 20);
    stats_kernel<<<DCH, 256>>>(RAW(2), g_m1, be_m1, scale+2*DCH, shift+2*DCH);

    // global branch (k=100)
    conv_kernel<false><<<TOTAL/8, 256>>>(verts, nbr, dirs_g0, 0, RAW(3), 100);
    stats_kernel<<<DCH, 256>>>(RAW(3), g_g0, be_g0, scale+3*DCH, shift+3*DCH);
    fo_kernel<<<TOTAL/32, 256>>>(RAW(3), scale+3*DCH, shift+3*DCH, W_g1, b_g1, fo);
    conv_kernel<true><<<TOTAL/8, 256>>>(verts, nbr, dirs_g1, fo, RAW(4), 100);
    stats_kernel<<<DCH, 256>>>(RAW(4), g_g1, be_g1, scale+4*DCH, shift+4*DCH);
    fo_kernel<<<TOTAL/32, 256>>>(RAW(4), scale+4*DCH, shift+4*DCH, W_g2, b_g2, fo);
    conv_kernel<true><<<TOTAL/8, 256>>>(verts, nbr, dirs_g2, fo, RAW(5), 100);
    stats_kernel<<<DCH, 256>>>(RAW(5), g_g2, be_g2, scale+5*DCH, shift+5*DCH);

    // fuse + down projection
    final_kernel<<<TOTAL/32, 256>>>(RAW(0), scale+0*DCH, shift+0*DCH,
                                    RAW(2), scale+2*DCH, shift+2*DCH,
                                    RAW(5), scale+5*DCH, shift+5*DCH,
                                    W_down, b_down, out);
#undef RAW
}

// round 2
// speedup vs baseline: 1.1724x; 1.1724x over previous
#include <cuda_runtime.h>
#include <math.h>
#include <float.h>

#define NPTS   1024
#define BATCH  4
#define TOTAL  (BATCH*NPTS)      // 4096
#define DCH    128
#define KMAX   100

// ---------------- scratch (static device globals; no allocation) ----------------
__device__ float4 g_nd[TOTAL*KMAX];          // normalized edge dirs + idx in .w
__device__ float  g_raw[6][TOTAL*DCH];       // raw (pre-BN) features per stage
__device__ float  g_fo[TOTAL*256];           // fm@W + bias buffer (reused)
__device__ float  g_scale[6*DCH];
__device__ float  g_shift[6*DCH];

// ---------------- f32x2 helpers -------------------------------------------------
__device__ __forceinline__ unsigned long long pack2(float a, float b) {
    unsigned long long r;
    asm("mov.b64 %0, {%1, %2};" : "=l"(r) : "f"(a), "f"(b));
    return r;
}
__device__ __forceinline__ void unpack2(unsigned long long v, float &a, float &b) {
    asm("mov.b64 {%0, %1}, %2;" : "=f"(a), "=f"(b) : "l"(v));
}
__device__ __forceinline__ void ffma2(unsigned long long &d, unsigned long long a, unsigned long long b) {
    asm("fma.rn.f32x2 %0, %1, %2, %3;" : "=l"(d) : "l"(a), "l"(b), "l"(d));
}

// ---------------- KNN + nd emit: warp per point, no barriers in loop ------------
__global__ __launch_bounds__(256) void knn_nd_kernel(const float* __restrict__ verts,
                                                     float4* __restrict__ nd)
{
    __shared__ float vx[NPTS], vy[NPTS], vz[NPTS];
    __shared__ unsigned int dk[8][NPTS];

    int tid = threadIdx.x;
    int p0  = blockIdx.x * 8;
    int b   = p0 >> 10;
    const float* vb = verts + b*NPTS*3;

    for (int t = tid; t < NPTS; t += 256) {
        vx[t] = vb[3*t+0]; vy[t] = vb[3*t+1]; vz[t] = vb[3*t+2];
    }
    __syncthreads();

    int warp = tid >> 5, lane = tid & 31;
    int p = p0 + warp;
    int i = p & (NPTS-1);
    float xi = vx[i], yi = vy[i], zi = vz[i];
    float sqi = xi*xi + yi*yi + zi*zi;

    unsigned int* dw = dk[warp];
    int jbase = lane * 32;

    unsigned long long gk0 = ~0ull, gk1 = ~0ull, gk2 = ~0ull, gk3 = ~0ull;
#pragma unroll
    for (int s = 0; s < 32; s++) {
        int j = jbase + s;
        float xj = vx[j], yj = vy[j], zj = vz[j];
        float sqj = xj*xj + yj*yj + zj*zj;
        float dot = xi*xj + yi*yj + zi*zj;
        float d   = sqi + sqj - 2.0f*dot;                    // same formula as reference
        unsigned int bits = __float_as_uint(d);
        unsigned int key  = (bits & 0x80000000u) ? ~bits : (bits | 0x80000000u);
        dw[j] = key;
        unsigned long long k64 = ((unsigned long long)key << 10) | (unsigned)j;
        if ((s>>3) == 0) gk0 = k64 < gk0 ? k64 : gk0;
        if ((s>>3) == 1) gk1 = k64 < gk1 ? k64 : gk1;
        if ((s>>3) == 2) gk2 = k64 < gk2 ? k64 : gk2;
        if ((s>>3) == 3) gk3 = k64 < gk3 ? k64 : gk3;
    }
    unsigned long long a01 = gk0 < gk1 ? gk0 : gk1;
    unsigned long long a23 = gk2 < gk3 ? gk2 : gk3;
    unsigned long long bk  = a01 < a23 ? a01 : a23;

    float4* ndp = nd + (size_t)p*KMAX;

    for (int t = 0; t <= KMAX; t++) {
        unsigned long long v = bk;
#pragma unroll
        for (int off = 16; off; off >>= 1) {
            unsigned long long v2 = __shfl_xor_sync(0xffffffffu, v, off);
            v = v2 < v ? v2 : v;
        }
        int w = (int)(v & 1023u);

        if (t > 0 && lane == 0) {
            float dx = vx[w]-xi, dy = vy[w]-yi, dz = vz[w]-zi;
            float inv = 1.0f / fmaxf(sqrtf(dx*dx + dy*dy + dz*dz), 1e-12f);
            ndp[t-1] = make_float4(dx*inv, dy*inv, dz*inv, __int_as_float(w));
        }

        if ((w >> 5) == lane) {
            dw[w] = 0xFFFFFFFFu;
            int g = (w >> 3) & 3;
            int base = jbase + g*8;
            unsigned long long ng = ~0ull;
#pragma unroll
            for (int s = 0; s < 8; s++) {
                int j = base + s;
                unsigned long long k64 = ((unsigned long long)dw[j] << 10) | (unsigned)j;
                ng = k64 < ng ? k64 : ng;
            }
            if (g == 0) gk0 = ng; else if (g == 1) gk1 = ng;
            else if (g == 2) gk2 = ng; else gk3 = ng;
            unsigned long long m01 = gk0 < gk1 ? gk0 : gk1;
            unsigned long long m23 = gk2 < gk3 ? gk2 : gk3;
            bk = m01 < m23 ? m01 : m23;
        }
    }
}

// ---------------- fused surface convs (k=5 -> raw0, k=20 -> raw1, k=100 -> raw3)
__global__ __launch_bounds__(256) void surf_fused_kernel(
    const float4* __restrict__ nd,
    const float* __restrict__ dl, const float* __restrict__ dm, const float* __restrict__ dg,
    float* __restrict__ raw_l, float* __restrict__ raw_m, float* __restrict__ raw_g)
{
    int lane = threadIdx.x & 31, warp = threadIdx.x >> 5;
    int p = blockIdx.x*8 + warp;
    int col0 = lane*4;

    float l0[4], l1[4], l2[4], m0[4], m1[4], m2[4], q0[4], q1[4], q2[4];
#pragma unroll
    for (int c = 0; c < 4; c++) {
        int col = col0 + c;
        float a0, a1, a2, inv;
        a0 = dl[col]; a1 = dl[128+col]; a2 = dl[256+col];
        inv = 1.0f / fmaxf(sqrtf(a0*a0+a1*a1+a2*a2), 1e-12f);
        l0[c]=a0*inv; l1[c]=a1*inv; l2[c]=a2*inv;
        a0 = dm[col]; a1 = dm[128+col]; a2 = dm[256+col];
        inv = 1.0f / fmaxf(sqrtf(a0*a0+a1*a1+a2*a2), 1e-12f);
        m0[c]=a0*inv; m1[c]=a1*inv; m2[c]=a2*inv;
        a0 = dg[col]; a1 = dg[128+col]; a2 = dg[256+col];
        inv = 1.0f / fmaxf(sqrtf(a0*a0+a1*a1+a2*a2), 1e-12f);
        q0[c]=a0*inv; q1[c]=a1*inv; q2[c]=a2*inv;
    }

    float accl[4] = {0,0,0,0}, accm[4] = {0,0,0,0}, accg[4] = {0,0,0,0};
    const float4* ndp = nd + (size_t)p*KMAX;

#pragma unroll 1
    for (int kk = 0; kk < 5; kk++) {
        float4 v = ndp[kk];
#pragma unroll
        for (int c = 0; c < 4; c++) {
            accl[c] = fmaxf(accl[c], v.x*l0[c] + v.y*l1[c] + v.z*l2[c]);
            accm[c] = fmaxf(accm[c], v.x*m0[c] + v.y*m1[c] + v.z*m2[c]);
            accg[c] = fmaxf(accg[c], v.x*q0[c] + v.y*q1[c] + v.z*q2[c]);
        }
    }
#pragma unroll 1
    for (int kk = 5; kk < 20; kk++) {
        float4 v = ndp[kk];
#pragma unroll
        for (int c = 0; c < 4; c++) {
            accm[c] = fmaxf(accm[c], v.x*m0[c] + v.y*m1[c] + v.z*m2[c]);
            accg[c] = fmaxf(accg[c], v.x*q0[c] + v.y*q1[c] + v.z*q2[c]);
        }
    }
#pragma unroll 2
    for (int kk = 20; kk < 100; kk++) {
        float4 v = ndp[kk];
#pragma unroll
        for (int c = 0; c < 4; c++)
            accg[c] = fmaxf(accg[c], v.x*q0[c] + v.y*q1[c] + v.z*q2[c]);
    }

    *(float4*)&raw_l[(size_t)p*DCH + col0] = make_float4(accl[0],accl[1],accl[2],accl[3]);
    *(float4*)&raw_m[(size_t)p*DCH + col0] = make_float4(accm[0],accm[1],accm[2],accm[3]);
    *(float4*)&raw_g[(size_t)p*DCH + col0] = make_float4(accg[0],accg[1],accg[2],accg[3]);
}

// ---------------- layer conv: warp per point, float4 gathers --------------------
__global__ __launch_bounds__(256) void conv_layer_kernel(
    const float4* __restrict__ nd, const float* __restrict__ fo,
    float* __restrict__ raw, int K)
{
    int lane = threadIdx.x & 31, warp = threadIdx.x >> 5;
    int p = blockIdx.x*8 + warp;
    int rowbase = p & ~(NPTS-1);          // b*1024
    int col0 = lane*4;

    float d0[4], d1[4], d2[4];
    // dirs normalized by caller? No: dirs passed raw -> normalize here (passed via fo? no)
    // dirs pointer packed into nd? -> pass separately:
    // (placeholder; real signature below)
    (void)d0; (void)d1; (void)d2;
    (void)rowbase; (void)col0; (void)p; (void)fo; (void)raw; (void)K; (void)nd;
}

// real layer conv (with dirs argument)
__global__ __launch_bounds__(256) void conv_layer(
    const float4* __restrict__ nd, const float* __restrict__ dirs,
    const float* __restrict__ fo, float* __restrict__ raw, int K)
{
    int lane = threadIdx.x & 31, warp = threadIdx.x >> 5;
    int p = blockIdx.x*8 + warp;
    int rowbase = p & ~(NPTS-1);
    int col0 = lane*4;

    float d0[4], d1[4], d2[4];
#pragma unroll
    for (int c = 0; c < 4; c++) {
        int col = col0 + c;
        float a0 = dirs[col], a1 = dirs[128+col], a2 = dirs[256+col];
        float inv = 1.0f / fmaxf(sqrtf(a0*a0+a1*a1+a2*a2), 1e-12f);
        d0[c]=a0*inv; d1[c]=a1*inv; d2[c]=a2*inv;
    }

    float acc[4] = {-FLT_MAX, -FLT_MAX, -FLT_MAX, -FLT_MAX};
    const float4* ndp = nd + (size_t)p*KMAX;

#pragma unroll 2
    for (int kk = 0; kk < K; kk++) {
        float4 v = ndp[kk];
        int j = __float_as_int(v.w);
        float4 fs = *(const float4*)(fo + (size_t)(rowbase + j)*256 + 128 + col0);
#pragma unroll
        for (int c = 0; c < 4; c++) {
            float th = fmaxf(v.x*d0[c] + v.y*d1[c] + v.z*d2[c], 0.0f);
            float f  = (c==0) ? fs.x : (c==1) ? fs.y : (c==2) ? fs.z : fs.w;
            acc[c] = fmaxf(acc[c], th*f);
        }
    }

    float4 fc = *(const float4*)(fo + (size_t)p*256 + col0);
    *(float4*)&raw[(size_t)p*DCH + col0] =
        make_float4(fc.x + acc[0], fc.y + acc[1], fc.z + acc[2], fc.w + acc[3]);
}

// ---------------- BN stats (4 channels per block) -------------------------------
__device__ __forceinline__ void stats_body(const float* __restrict__ raw,
                                           const float* __restrict__ g,
                                           const float* __restrict__ be,
                                           float* __restrict__ scale,
                                           float* __restrict__ shift, int c4)
{
    int tid = threadIdx.x;
    float s0=0,s1=0,s2=0,s3=0,q0=0,q1=0,q2=0,q3=0;
    for (int r = tid; r < TOTAL; r += 256) {
        float4 v = *(const float4*)(raw + (size_t)r*DCH + c4);
        s0 += v.x; q0 += v.x*v.x;
        s1 += v.y; q1 += v.y*v.y;
        s2 += v.z; q2 += v.z*v.z;
        s3 += v.w; q3 += v.w*v.w;
    }
#pragma unroll
    for (int off = 16; off; off >>= 1) {
        s0 += __shfl_xor_sync(0xffffffffu, s0, off);
        s1 += __shfl_xor_sync(0xffffffffu, s1, off);
        s2 += __shfl_xor_sync(0xffffffffu, s2, off);
        s3 += __shfl_xor_sync(0xffffffffu, s3, off);
        q0 += __shfl_xor_sync(0xffffffffu, q0, off);
        q1 += __shfl_xor_sync(0xffffffffu, q1, off);
        q2 += __shfl_xor_sync(0xffffffffu, q2, off);
        q3 += __shfl_xor_sync(0xffffffffu, q3, off);
    }
    __shared__ float red[8][8];
    int warp = tid >> 5, lane = tid & 31;
    if (lane == 0) {
        red[warp][0]=s0; red[warp][1]=s1; red[warp][2]=s2; red[warp][3]=s3;
        red[warp][4]=q0; red[warp][5]=q1; red[warp][6]=q2; red[warp][7]=q3;
    }
    __syncthreads();
    if (tid < 8) {
        float t = 0.f;
#pragma unroll
        for (int w = 0; w < 8; w++) t += red[w][tid];
        red[0][tid] = t;
    }
    __syncthreads();
    if (tid < 4) {
        float mean = red[0][tid] * (1.0f/TOTAL);
        float var  = fmaxf(red[0][4+tid] * (1.0f/TOTAL) - mean*mean, 0.f);
        float sc   = g[c4+tid] * rsqrtf(var + 1e-5f);
        scale[c4+tid] = sc;
        shift[c4+tid] = be[c4+tid] - mean*sc;
    }
}

__global__ __launch_bounds__(256) void stats1_kernel(const float* raw, const float* g,
                                                     const float* be, float* scale, float* shift)
{
    stats_body(raw, g, be, scale, shift, blockIdx.x*4);
}

__global__ __launch_bounds__(256) void stats3_kernel(
    const float* r0, const float* g0, const float* b0, float* sc0, float* sh0,
    const float* r1, const float* g1, const float* b1, float* sc1, float* sh1,
    const float* r2, const float* g2, const float* b2, float* sc2, float* sh2)
{
    int stage = blockIdx.x >> 5;
    int c4 = (blockIdx.x & 31) * 4;
    if (stage == 0)      stats_body(r0, g0, b0, sc0, sh0, c4);
    else if (stage == 1) stats_body(r1, g1, b1, sc1, sh1, c4);
    else                 stats_body(r2, g2, b2, sc2, sh2, c4);
}

// ---------------- GEMM (f32x2): fo = bn_relu(raw) @ W + bias --------------------
__global__ __launch_bounds__(256) void gemm_fo_kernel(
    const float* __restrict__ raw, const float* __restrict__ scale,
    const float* __restrict__ shift, const float* __restrict__ W,
    const float* __restrict__ bias, float* __restrict__ fo)
{
    __shared__ float4 in_s[64*16];        // [kpair][rowpair] packed {r0k0,r1k0,r0k1,r1k1}
    int tid = threadIdx.x;
    int r0 = blockIdx.x * 32;

    for (int idx = tid; idx < 32*128; idx += 256) {
        int r = idx >> 7, k = idx & 127;
        float x = raw[(size_t)(r0+r)*DCH + k];
        float val = fmaxf(fmaf(x, scale[k], shift[k]), 0.f);
        float* cell = (float*)&in_s[(k>>1)*16 + (r>>1)];
        cell[(r&1) | ((k&1)<<1)] = val;
    }
    __syncthreads();

    unsigned long long acc[16];
#pragma unroll
    for (int rp = 0; rp < 16; rp++) acc[rp] = 0ull;

#pragma unroll 2
    for (int pk = 0; pk < 64; pk++) {
        float w0 = W[(2*pk+0)*256 + tid];
        float w1 = W[(2*pk+1)*256 + tid];
        unsigned long long w0p = pack2(w0, w0);
        unsigned long long w1p = pack2(w1, w1);
        const ulonglong2* row = (const ulonglong2*)(in_s + pk*16);
#pragma unroll
        for (int rp = 0; rp < 16; rp++) {
            ulonglong2 v = row[rp];
            ffma2(acc[rp], v.x, w0p);
            ffma2(acc[rp], v.y, w1p);
        }
    }

    float bb = bias[tid];
#pragma unroll
    for (int rp = 0; rp < 16; rp++) {
        float lo, hi;
        unpack2(acc[rp], lo, hi);
        fo[(size_t)(r0 + 2*rp + 0)*256 + tid] = lo + bb;
        fo[(size_t)(r0 + 2*rp + 1)*256 + tid] = hi + bb;
    }
}

// ---------------- final GEMM (f32x2, concat-3 input, relu) ----------------------
__global__ __launch_bounds__(256) void gemm_final_kernel(
    const float* __restrict__ rl, const float* __restrict__ scl, const float* __restrict__ shl,
    const float* __restrict__ rm, const float* __restrict__ scm, const float* __restrict__ shm,
    const float* __restrict__ rg, const float* __restrict__ scg, const float* __restrict__ shg,
    const float* __restrict__ Wd, const float* __restrict__ bd,
    float* __restrict__ out)
{
    __shared__ float4 in_s[192*16];       // 48KB exactly
    int tid = threadIdx.x;
    int r0 = blockIdx.x * 32;

    for (int idx = tid; idx < 32*384; idx += 256) {
        int r = idx / 384;
        int k = idx - r*384;
        float x, sc, sh;
        if (k < 128)      { x = rl[(size_t)(r0+r)*DCH + k];       sc = scl[k];     sh = shl[k]; }
        else if (k < 256) { x = rm[(size_t)(r0+r)*DCH + (k-128)]; sc = scm[k-128]; sh = shm[k-128]; }
        else              { x = rg[(size_t)(r0+r)*DCH + (k-256)]; sc = scg[k-256]; sh = shg[k-256]; }
        float val = fmaxf(fmaf(x, sc, sh), 0.f);
        float* cell = (float*)&in_s[(k>>1)*16 + (r>>1)];
        cell[(r&1) | ((k&1)<<1)] = val;
    }
    __syncthreads();

    unsigned long long acc[16];
#pragma unroll
    for (int rp = 0; rp < 16; rp++) acc[rp] = 0ull;

#pragma unroll 2
    for (int pk = 0; pk < 192; pk++) {
        float w0 = Wd[(2*pk+0)*256 + tid];
        float w1 = Wd[(2*pk+1)*256 + tid];
        unsigned long long w0p = pack2(w0, w0);
        unsigned long long w1p = pack2(w1, w1);
        const ulonglong2* row = (const ulonglong2*)(in_s + pk*16);
#pragma unroll
        for (int rp = 0; rp < 16; rp++) {
            ulonglong2 v = row[rp];
            ffma2(acc[rp], v.x, w0p);
            ffma2(acc[rp], v.y, w1p);
        }
    }

    float bb = bd[tid];
#pragma unroll
    for (int rp = 0; rp < 16; rp++) {
        float lo, hi;
        unpack2(acc[rp], lo, hi);
        out[(size_t)(r0 + 2*rp + 0)*256 + tid] = fmaxf(lo + bb, 0.f);
        out[(size_t)(r0 + 2*rp + 1)*256 + tid] = fmaxf(hi + bb, 0.f);
    }
}

// ---------------- launcher ------------------------------------------------------
extern "C" void kernel_launch(void* const* d_in, const int* in_sizes, int n_in,
                              void* d_out, int out_size)
{
    const float* verts   = (const float*)d_in[0];
    const float* dirs_l  = (const float*)d_in[1];
    const float* dirs_m0 = (const float*)d_in[2];
    const float* W_m1    = (const float*)d_in[3];
    const float* b_m1    = (const float*)d_in[4];
    const float* dirs_m1 = (const float*)d_in[5];
    const float* dirs_g0 = (const float*)d_in[6];
    const float* W_g1    = (const float*)d_in[7];
    const float* b_g1    = (const float*)d_in[8];
    const float* dirs_g1 = (const float*)d_in[9];
    const float* W_g2    = (const float*)d_in[10];
    const float* b_g2    = (const float*)d_in[11];
    const float* dirs_g2 = (const float*)d_in[12];
    const float* g_l   = (const float*)d_in[13];
    const float* be_l  = (const float*)d_in[14];
    const float* g_m0  = (const float*)d_in[15];
    const float* be_m0 = (const float*)d_in[16];
    const float* g_m1  = (const float*)d_in[17];
    const float* be_m1 = (const float*)d_in[18];
    const float* g_g0  = (const float*)d_in[19];
    const float* be_g0 = (const float*)d_in[20];
    const float* g_g1  = (const float*)d_in[21];
    const float* be_g1 = (const float*)d_in[22];
    const float* g_g2  = (const float*)d_in[23];
    const float* be_g2 = (const float*)d_in[24];
    const float* W_down = (const float*)d_in[25];
    const float* b_down = (const float*)d_in[26];
    float* out = (float*)d_out;

    float4* nd;   cudaGetSymbolAddress((void**)&nd,    g_nd);
    float*  raw;  cudaGetSymbolAddress((void**)&raw,   g_raw);
    float*  fo;   cudaGetSymbolAddress((void**)&fo,    g_fo);
    float*  scale;cudaGetSymbolAddress((void**)&scale, g_scale);
    float*  shift;cudaGetSymbolAddress((void**)&shift, g_shift);

#define RAW(s) (raw + (size_t)(s)*TOTAL*DCH)
#define SC(s)  (scale + (s)*DCH)
#define SH(s)  (shift + (s)*DCH)

    knn_nd_kernel<<<TOTAL/8, 256>>>(verts, nd);

    surf_fused_kernel<<<TOTAL/8, 256>>>(nd, dirs_l, dirs_m0, dirs_g0,
                                        RAW(0), RAW(1), RAW(3));
    stats3_kernel<<<96, 256>>>(RAW(0), g_l,  be_l,  SC(0), SH(0),
                               RAW(1), g_m0, be_m0, SC(1), SH(1),
                               RAW(3), g_g0, be_g0, SC(3), SH(3));

    // medium branch
    gemm_fo_kernel<<<TOTAL/32, 256>>>(RAW(1), SC(1), SH(1), W_m1, b_m1, fo);
    conv_layer<<<TOTAL/8, 256>>>(nd, dirs_m1, fo, RAW(2), 20);
    stats1_kernel<<<32, 256>>>(RAW(2), g_m1, be_m1, SC(2), SH(2));

    // global branch
    gemm_fo_kernel<<<TOTAL/32, 256>>>(RAW(3), SC(3), SH(3), W_g1, b_g1, fo);
    conv_layer<<<TOTAL/8, 256>>>(nd, dirs_g1, fo, RAW(4), 100);
    stats1_kernel<<<32, 256>>>(RAW(4), g_g1, be_g1, SC(4), SH(4));

    gemm_fo_kernel<<<TOTAL/32, 256>>>(RAW(4), SC(4), SH(4), W_g2, b_g2, fo);
    conv_layer<<<TOTAL/8, 256>>>(nd, dirs_g2, fo, RAW(5), 100);
    stats1_kernel<<<32, 256>>>(RAW(5), g_g2, be_g2, SC(5), SH(5));

    gemm_final_kernel<<<TOTAL/32, 256>>>(RAW(0), SC(0), SH(0),
                                         RAW(2), SC(2), SH(2),
                                         RAW(5), SC(5), SH(5),
                                         W_down, b_down, out);
#undef RAW
#undef SC
#undef SH
}

// round 3
// speedup vs baseline: 1.3378x; 1.1411x over previous
#include <cuda_runtime.h>
#include <math.h>
#include <float.h>

#define NPTS   1024
#define BATCH  4
#define TOTAL  (BATCH*NPTS)      // 4096
#define DCH    128
#define KMAX   100

// ---------------- scratch (static device globals; no allocation) ----------------
__device__ float4 g_nd[TOTAL*KMAX];          // normalized edge dirs + idx in .w
__device__ float  g_raw[6][TOTAL*DCH];       // raw (pre-BN) features per stage
__device__ float  g_fc_m[TOTAL*DCH];
__device__ float  g_fs_m[TOTAL*DCH];
__device__ float  g_fc_g[TOTAL*DCH];
__device__ float  g_fs_g[TOTAL*DCH];
__device__ float  g_scale[6*DCH];
__device__ float  g_shift[6*DCH];

// ---------------- f32x2 helpers -------------------------------------------------
__device__ __forceinline__ unsigned long long pack2(float a, float b) {
    unsigned long long r;
    asm("mov.b64 %0, {%1, %2};" : "=l"(r) : "f"(a), "f"(b));
    return r;
}
__device__ __forceinline__ void unpack2(unsigned long long v, float &a, float &b) {
    asm("mov.b64 {%0, %1}, %2;" : "=f"(a), "=f"(b) : "l"(v));
}
__device__ __forceinline__ void ffma2(unsigned long long &d, unsigned long long a, unsigned long long b) {
    asm("fma.rn.f32x2 %0, %1, %2, %3;" : "=l"(d) : "l"(a), "l"(b), "l"(d));
}

// ================= KNN + fused surface convs =====================================
__global__ __launch_bounds__(256) void knn_surf_kernel(
    const float* __restrict__ verts, float4* __restrict__ nd,
    float* __restrict__ raw_l, float* __restrict__ raw_m, float* __restrict__ raw_g,
    const float* __restrict__ dl, const float* __restrict__ dm, const float* __restrict__ dg)
{
    __shared__ float vx[NPTS], vy[NPTS], vz[NPTS];
    __shared__ unsigned int dk[8][NPTS];

    int tid = threadIdx.x;
    int p0  = blockIdx.x * 8;
    int b   = p0 >> 10;
    const float* vb = verts + b*NPTS*3;

    for (int t = tid; t < NPTS; t += 256) {
        vx[t] = vb[3*t+0]; vy[t] = vb[3*t+1]; vz[t] = vb[3*t+2];
    }
    __syncthreads();

    int warp = tid >> 5, lane = tid & 31;
    int p = p0 + warp;
    int i = p & (NPTS-1);
    float xi = vx[i], yi = vy[i], zi = vz[i];
    float sqi = xi*xi + yi*yi + zi*zi;

    unsigned int* dw = dk[warp];
    int jbase = lane * 32;

    unsigned long long gk0 = ~0ull, gk1 = ~0ull, gk2 = ~0ull, gk3 = ~0ull;
#pragma unroll
    for (int s = 0; s < 32; s++) {
        int j = jbase + s;
        float xj = vx[j], yj = vy[j], zj = vz[j];
        float sqj = xj*xj + yj*yj + zj*zj;
        float dot = xi*xj + yi*yj + zi*zj;
        float d   = sqi + sqj - 2.0f*dot;                    // same formula as reference
        unsigned int bits = __float_as_uint(d);
        unsigned int key  = (bits & 0x80000000u) ? ~bits : (bits | 0x80000000u);
        dw[j] = key;
        unsigned long long k64 = ((unsigned long long)key << 10) | (unsigned)j;
        if ((s>>3) == 0) gk0 = k64 < gk0 ? k64 : gk0;
        if ((s>>3) == 1) gk1 = k64 < gk1 ? k64 : gk1;
        if ((s>>3) == 2) gk2 = k64 < gk2 ? k64 : gk2;
        if ((s>>3) == 3) gk3 = k64 < gk3 ? k64 : gk3;
    }
    unsigned long long a01 = gk0 < gk1 ? gk0 : gk1;
    unsigned long long a23 = gk2 < gk3 ? gk2 : gk3;
    unsigned long long bk  = a01 < a23 ? a01 : a23;

    float4* ndp = nd + (size_t)p*KMAX;

    for (int t = 0; t <= KMAX; t++) {
        unsigned long long v = bk;
#pragma unroll
        for (int off = 16; off; off >>= 1) {
            unsigned long long v2 = __shfl_xor_sync(0xffffffffu, v, off);
            v = v2 < v ? v2 : v;
        }
        int w = (int)(v & 1023u);

        if (t > 0 && lane == 0) {
            float dx = vx[w]-xi, dy = vy[w]-yi, dz = vz[w]-zi;
            float inv = 1.0f / fmaxf(sqrtf(dx*dx + dy*dy + dz*dz), 1e-12f);
            ndp[t-1] = make_float4(dx*inv, dy*inv, dz*inv, __int_as_float(w));
        }

        if ((w >> 5) == lane) {
            dw[w] = 0xFFFFFFFFu;
            int g = (w >> 3) & 3;
            int base = jbase + g*8;
            unsigned long long ng = ~0ull;
#pragma unroll
            for (int s = 0; s < 8; s++) {
                int j = base + s;
                unsigned long long k64 = ((unsigned long long)dw[j] << 10) | (unsigned)j;
                ng = k64 < ng ? k64 : ng;
            }
            if (g == 0) gk0 = ng; else if (g == 1) gk1 = ng;
            else if (g == 2) gk2 = ng; else gk3 = ng;
            unsigned long long m01 = gk0 < gk1 ? gk0 : gk1;
            unsigned long long m23 = gk2 < gk3 ? gk2 : gk3;
            bk = m01 < m23 ? m01 : m23;
        }
    }
    __syncwarp();

    // -------- fused surface convs on this point's nd list --------
    int col0 = lane*4;
    float l0[4], l1[4], l2[4], m0[4], m1[4], m2[4], q0[4], q1[4], q2[4];
#pragma unroll
    for (int c = 0; c < 4; c++) {
        int col = col0 + c;
        float a0, a1, a2, inv;
        a0 = dl[col]; a1 = dl[128+col]; a2 = dl[256+col];
        inv = 1.0f / fmaxf(sqrtf(a0*a0+a1*a1+a2*a2), 1e-12f);
        l0[c]=a0*inv; l1[c]=a1*inv; l2[c]=a2*inv;
        a0 = dm[col]; a1 = dm[128+col]; a2 = dm[256+col];
        inv = 1.0f / fmaxf(sqrtf(a0*a0+a1*a1+a2*a2), 1e-12f);
        m0[c]=a0*inv; m1[c]=a1*inv; m2[c]=a2*inv;
        a0 = dg[col]; a1 = dg[128+col]; a2 = dg[256+col];
        inv = 1.0f / fmaxf(sqrtf(a0*a0+a1*a1+a2*a2), 1e-12f);
        q0[c]=a0*inv; q1[c]=a1*inv; q2[c]=a2*inv;
    }

    float accl[4] = {0,0,0,0}, accm[4] = {0,0,0,0}, accg[4] = {0,0,0,0};
#pragma unroll 1
    for (int kk = 0; kk < 5; kk++) {
        float4 v = ndp[kk];
#pragma unroll
        for (int c = 0; c < 4; c++) {
            accl[c] = fmaxf(accl[c], v.x*l0[c] + v.y*l1[c] + v.z*l2[c]);
            accm[c] = fmaxf(accm[c], v.x*m0[c] + v.y*m1[c] + v.z*m2[c]);
            accg[c] = fmaxf(accg[c], v.x*q0[c] + v.y*q1[c] + v.z*q2[c]);
        }
    }
#pragma unroll 1
    for (int kk = 5; kk < 20; kk++) {
        float4 v = ndp[kk];
#pragma unroll
        for (int c = 0; c < 4; c++) {
            accm[c] = fmaxf(accm[c], v.x*m0[c] + v.y*m1[c] + v.z*m2[c]);
            accg[c] = fmaxf(accg[c], v.x*q0[c] + v.y*q1[c] + v.z*q2[c]);
        }
    }
#pragma unroll 4
    for (int kk = 20; kk < 100; kk++) {
        float4 v = ndp[kk];
#pragma unroll
        for (int c = 0; c < 4; c++)
            accg[c] = fmaxf(accg[c], v.x*q0[c] + v.y*q1[c] + v.z*q2[c]);
    }

    *(float4*)&raw_l[(size_t)p*DCH + col0] = make_float4(accl[0],accl[1],accl[2],accl[3]);
    *(float4*)&raw_m[(size_t)p*DCH + col0] = make_float4(accm[0],accm[1],accm[2],accm[3]);
    *(float4*)&raw_g[(size_t)p*DCH + col0] = make_float4(accg[0],accg[1],accg[2],accg[3]);
}

// ================= GEMM core: 16 rows x 256 cols, k-pair f32x2 ===================
// thread: 4 cols x 4 rows. in_s[r][kp] holds (a[2kp], a[2kp+1]) for row r.
struct GemmSmem { unsigned long long in_s[16][65]; };

template<bool RELU>
__device__ __forceinline__ void gemm16_body(
    GemmSmem* sm,
    const float* __restrict__ A, const float* __restrict__ sc, const float* __restrict__ sh,
    const float* __restrict__ W, const float* __restrict__ bias,
    float* __restrict__ outc, float* __restrict__ outs, int r0)
{
    int tid = threadIdx.x;
#pragma unroll
    for (int it = 0; it < 8; it++) {
        int idx = tid + it*256;
        int r = idx >> 7, k = idx & 127;
        float x = A[(size_t)(r0+r)*DCH + k];
        float val = fmaxf(fmaf(x, sc[k], sh[k]), 0.f);
        ((float*)&sm->in_s[r][k>>1])[k&1] = val;
    }
    __syncthreads();

    int col0 = (tid & 63) * 4;
    int rg   = tid >> 6;
    const unsigned long long* A0 = sm->in_s[rg*4+0];
    const unsigned long long* A1 = sm->in_s[rg*4+1];
    const unsigned long long* A2 = sm->in_s[rg*4+2];
    const unsigned long long* A3 = sm->in_s[rg*4+3];

    unsigned long long acc[4][4];
#pragma unroll
    for (int c = 0; c < 4; c++)
#pragma unroll
        for (int r = 0; r < 4; r++) acc[c][r] = 0ull;

    float4 wa = *(const float4*)(W + 0*256 + col0);
    float4 wb = *(const float4*)(W + 1*256 + col0);

#pragma unroll 4
    for (int pk = 0; pk < 64; pk++) {
        int np = pk < 63 ? pk + 1 : 63;
        float4 wan = *(const float4*)(W + (2*np+0)*256 + col0);
        float4 wbn = *(const float4*)(W + (2*np+1)*256 + col0);

        unsigned long long w0 = pack2(wa.x, wb.x);
        unsigned long long w1 = pack2(wa.y, wb.y);
        unsigned long long w2 = pack2(wa.z, wb.z);
        unsigned long long w3 = pack2(wa.w, wb.w);
        unsigned long long a0 = A0[pk], a1 = A1[pk], a2 = A2[pk], a3 = A3[pk];

        ffma2(acc[0][0], a0, w0); ffma2(acc[0][1], a1, w0);
        ffma2(acc[0][2], a2, w0); ffma2(acc[0][3], a3, w0);
        ffma2(acc[1][0], a0, w1); ffma2(acc[1][1], a1, w1);
        ffma2(acc[1][2], a2, w1); ffma2(acc[1][3], a3, w1);
        ffma2(acc[2][0], a0, w2); ffma2(acc[2][1], a1, w2);
        ffma2(acc[2][2], a2, w2); ffma2(acc[2][3], a3, w2);
        ffma2(acc[3][0], a0, w3); ffma2(acc[3][1], a1, w3);
        ffma2(acc[3][2], a2, w3); ffma2(acc[3][3], a3, w3);

        wa = wan; wb = wbn;
    }

    float4 bb = *(const float4*)(bias + col0);
    float* dst; int cbase;
    if (outs && col0 >= 128) { dst = outs; cbase = col0 - 128; }
    else if (outs)           { dst = outc; cbase = col0; }
    else                     { dst = outc; cbase = col0; }
    int stride = outs ? DCH : 256;

#pragma unroll
    for (int r = 0; r < 4; r++) {
        float v0, v1, v2, v3, lo, hi;
        unpack2(acc[0][r], lo, hi); v0 = lo + hi + bb.x;
        unpack2(acc[1][r], lo, hi); v1 = lo + hi + bb.y;
        unpack2(acc[2][r], lo, hi); v2 = lo + hi + bb.z;
        unpack2(acc[3][r], lo, hi); v3 = lo + hi + bb.w;
        if (RELU) { v0=fmaxf(v0,0.f); v1=fmaxf(v1,0.f); v2=fmaxf(v2,0.f); v3=fmaxf(v3,0.f); }
        int row = r0 + rg*4 + r;
        *(float4*)&dst[(size_t)row*stride + cbase] = make_float4(v0,v1,v2,v3);
    }
}

__global__ __launch_bounds__(256) void gemm_split_kernel(
    const float* A, const float* sc, const float* sh,
    const float* W, const float* bias, float* fc, float* fs)
{
    __shared__ GemmSmem sm;
    gemm16_body<false>(&sm, A, sc, sh, W, bias, fc, fs, blockIdx.x*16);
}

__global__ __launch_bounds__(256) void gemm_dual_kernel(
    const float* A0, const float* sc0, const float* sh0, const float* W0, const float* b0,
    float* fc0, float* fs0,
    const float* A1, const float* sc1, const float* sh1, const float* W1, const float* b1,
    float* fc1, float* fs1)
{
    __shared__ GemmSmem sm;
    int bid = blockIdx.x;
    if (bid < 256) gemm16_body<false>(&sm, A0, sc0, sh0, W0, b0, fc0, fs0, bid*16);
    else           gemm16_body<false>(&sm, A1, sc1, sh1, W1, b1, fc1, fs1, (bid-256)*16);
}

// ---------------- final GEMM: K=384 (3 BN'd sources), relu ----------------------
__global__ __launch_bounds__(256) void gemm_final_kernel(
    const float* __restrict__ rl, const float* __restrict__ scl, const float* __restrict__ shl,
    const float* __restrict__ rm, const float* __restrict__ scm, const float* __restrict__ shm,
    const float* __restrict__ rg, const float* __restrict__ scg, const float* __restrict__ shg,
    const float* __restrict__ Wd, const float* __restrict__ bd, float* __restrict__ out)
{
    __shared__ unsigned long long in_s[16][193];
    int tid = threadIdx.x;
    int r0 = blockIdx.x * 16;

    const float* srcs[3] = {rl, rm, rg};
    const float* scs[3]  = {scl, scm, scg};
    const float* shs[3]  = {shl, shm, shg};
#pragma unroll
    for (int s = 0; s < 3; s++) {
        const float* A = srcs[s]; const float* sc = scs[s]; const float* sh = shs[s];
#pragma unroll
        for (int it = 0; it < 8; it++) {
            int idx = tid + it*256;
            int r = idx >> 7, k = idx & 127;
            float x = A[(size_t)(r0+r)*DCH + k];
            float val = fmaxf(fmaf(x, sc[k], sh[k]), 0.f);
            ((float*)&in_s[r][64*s + (k>>1)])[k&1] = val;
        }
    }
    __syncthreads();

    int col0 = (tid & 63) * 4;
    int rg_  = tid >> 6;
    const unsigned long long* A0 = in_s[rg_*4+0];
    const unsigned long long* A1 = in_s[rg_*4+1];
    const unsigned long long* A2 = in_s[rg_*4+2];
    const unsigned long long* A3 = in_s[rg_*4+3];

    unsigned long long acc[4][4];
#pragma unroll
    for (int c = 0; c < 4; c++)
#pragma unroll
        for (int r = 0; r < 4; r++) acc[c][r] = 0ull;

    float4 wa = *(const float4*)(Wd + 0*256 + col0);
    float4 wb = *(const float4*)(Wd + 1*256 + col0);

#pragma unroll 4
    for (int pk = 0; pk < 192; pk++) {
        int np = pk < 191 ? pk + 1 : 191;
        float4 wan = *(const float4*)(Wd + (2*np+0)*256 + col0);
        float4 wbn = *(const float4*)(Wd + (2*np+1)*256 + col0);

        unsigned long long w0 = pack2(wa.x, wb.x);
        unsigned long long w1 = pack2(wa.y, wb.y);
        unsigned long long w2 = pack2(wa.z, wb.z);
        unsigned long long w3 = pack2(wa.w, wb.w);
        unsigned long long a0 = A0[pk], a1 = A1[pk], a2 = A2[pk], a3 = A3[pk];

        ffma2(acc[0][0], a0, w0); ffma2(acc[0][1], a1, w0);
        ffma2(acc[0][2], a2, w0); ffma2(acc[0][3], a3, w0);
        ffma2(acc[1][0], a0, w1); ffma2(acc[1][1], a1, w1);
        ffma2(acc[1][2], a2, w1); ffma2(acc[1][3], a3, w1);
        ffma2(acc[2][0], a0, w2); ffma2(acc[2][1], a1, w2);
        ffma2(acc[2][2], a2, w2); ffma2(acc[2][3], a3, w2);
        ffma2(acc[3][0], a0, w3); ffma2(acc[3][1], a1, w3);
        ffma2(acc[3][2], a2, w3); ffma2(acc[3][3], a3, w3);

        wa = wan; wb = wbn;
    }

    float4 bb = *(const float4*)(bd + col0);
#pragma unroll
    for (int r = 0; r < 4; r++) {
        float v0, v1, v2, v3, lo, hi;
        unpack2(acc[0][r], lo, hi); v0 = fmaxf(lo + hi + bb.x, 0.f);
        unpack2(acc[1][r], lo, hi); v1 = fmaxf(lo + hi + bb.y, 0.f);
        unpack2(acc[2][r], lo, hi); v2 = fmaxf(lo + hi + bb.z, 0.f);
        unpack2(acc[3][r], lo, hi); v3 = fmaxf(lo + hi + bb.w, 0.f);
        int row = r0 + rg_*4 + r;
        *(float4*)&out[(size_t)row*256 + col0] = make_float4(v0,v1,v2,v3);
    }
}

// ================= layer conv ====================================================
__device__ __forceinline__ void conv_body(
    const float4* __restrict__ nd, const float* __restrict__ dirs,
    const float* __restrict__ fc, const float* __restrict__ fs,
    float* __restrict__ raw, int K, int p)
{
    int lane = threadIdx.x & 31;
    int rowbase = p & ~(NPTS-1);
    int col0 = lane*4;

    float d0[4], d1[4], d2[4];
#pragma unroll
    for (int c = 0; c < 4; c++) {
        int col = col0 + c;
        float a0 = dirs[col], a1 = dirs[128+col], a2 = dirs[256+col];
        float inv = 1.0f / fmaxf(sqrtf(a0*a0+a1*a1+a2*a2), 1e-12f);
        d0[c]=a0*inv; d1[c]=a1*inv; d2[c]=a2*inv;
    }

    float acc[4] = {-FLT_MAX, -FLT_MAX, -FLT_MAX, -FLT_MAX};
    const float4* ndp = nd + (size_t)p*KMAX;

#pragma unroll 4
    for (int kk = 0; kk < K; kk++) {
        float4 v = ndp[kk];
        int j = __float_as_int(v.w);
        float4 f = *(const float4*)(fs + (size_t)(rowbase + j)*DCH + col0);
        float t0 = fmaxf(v.x*d0[0] + v.y*d1[0] + v.z*d2[0], 0.0f);
        float t1 = fmaxf(v.x*d0[1] + v.y*d1[1] + v.z*d2[1], 0.0f);
        float t2 = fmaxf(v.x*d0[2] + v.y*d1[2] + v.z*d2[2], 0.0f);
        float t3 = fmaxf(v.x*d0[3] + v.y*d1[3] + v.z*d2[3], 0.0f);
        acc[0] = fmaxf(acc[0], t0*f.x);
        acc[1] = fmaxf(acc[1], t1*f.y);
        acc[2] = fmaxf(acc[2], t2*f.z);
        acc[3] = fmaxf(acc[3], t3*f.w);
    }

    float4 c4 = *(const float4*)(fc + (size_t)p*DCH + col0);
    *(float4*)&raw[(size_t)p*DCH + col0] =
        make_float4(c4.x + acc[0], c4.y + acc[1], c4.z + acc[2], c4.w + acc[3]);
}

__global__ __launch_bounds__(256) void conv_dual_kernel(
    const float4* nd,
    const float* dirs_m, const float* fc_m, const float* fs_m, float* raw_m,
    const float* dirs_g, const float* fc_g, const float* fs_g, float* raw_g)
{
    int bid = blockIdx.x, warp = threadIdx.x >> 5;
    if (bid < 512) conv_body(nd, dirs_m, fc_m, fs_m, raw_m, 20,  bid*8 + warp);
    else           conv_body(nd, dirs_g, fc_g, fs_g, raw_g, 100, (bid-512)*8 + warp);
}

__global__ __launch_bounds__(256) void conv_single_kernel(
    const float4* nd, const float* dirs, const float* fc, const float* fs, float* raw)
{
    conv_body(nd, dirs, fc, fs, raw, 100, blockIdx.x*8 + (threadIdx.x >> 5));
}

// ================= BN stats ======================================================
__device__ __forceinline__ void stats_body(const float* __restrict__ raw,
                                           const float* __restrict__ g,
                                           const float* __restrict__ be,
                                           float* __restrict__ scale,
                                           float* __restrict__ shift, int c4)
{
    int tid = threadIdx.x;
    float s0=0,s1=0,s2=0,s3=0,q0=0,q1=0,q2=0,q3=0;
    for (int r = tid; r < TOTAL; r += 256) {
        float4 v = *(const float4*)(raw + (size_t)r*DCH + c4);
        s0 += v.x; q0 += v.x*v.x;
        s1 += v.y; q1 += v.y*v.y;
        s2 += v.z; q2 += v.z*v.z;
        s3 += v.w; q3 += v.w*v.w;
    }
#pragma unroll
    for (int off = 16; off; off >>= 1) {
        s0 += __shfl_xor_sync(0xffffffffu, s0, off);
        s1 += __shfl_xor_sync(0xffffffffu, s1, off);
        s2 += __shfl_xor_sync(0xffffffffu, s2, off);
        s3 += __shfl_xor_sync(0xffffffffu, s3, off);
        q0 += __shfl_xor_sync(0xffffffffu, q0, off);
        q1 += __shfl_xor_sync(0xffffffffu, q1, off);
        q2 += __shfl_xor_sync(0xffffffffu, q2, off);
        q3 += __shfl_xor_sync(0xffffffffu, q3, off);
    }
    __shared__ float red[8][8];
    int warp = tid >> 5, lane = tid & 31;
    if (lane == 0) {
        red[warp][0]=s0; red[warp][1]=s1; red[warp][2]=s2; red[warp][3]=s3;
        red[warp][4]=q0; red[warp][5]=q1; red[warp][6]=q2; red[warp][7]=q3;
    }
    __syncthreads();
    if (tid < 8) {
        float t = 0.f;
#pragma unroll
        for (int w = 0; w < 8; w++) t += red[w][tid];
        red[0][tid] = t;
    }
    __syncthreads();
    if (tid < 4) {
        float mean = red[0][tid] * (1.0f/TOTAL);
        float var  = fmaxf(red[0][4+tid] * (1.0f/TOTAL) - mean*mean, 0.f);
        float sc   = g[c4+tid] * rsqrtf(var + 1e-5f);
        scale[c4+tid] = sc;
        shift[c4+tid] = be[c4+tid] - mean*sc;
    }
}

__global__ __launch_bounds__(256) void stats1_kernel(const float* raw, const float* g,
                                                     const float* be, float* scale, float* shift)
{
    stats_body(raw, g, be, scale, shift, blockIdx.x*4);
}

__global__ __launch_bounds__(256) void stats2_kernel(
    const float* r0, const float* g0, const float* b0, float* sc0, float* sh0,
    const float* r1, const float* g1, const float* b1, float* sc1, float* sh1)
{
    int stage = blockIdx.x >> 5;
    int c4 = (blockIdx.x & 31) * 4;
    if (stage == 0) stats_body(r0, g0, b0, sc0, sh0, c4);
    else            stats_body(r1, g1, b1, sc1, sh1, c4);
}

__global__ __launch_bounds__(256) void stats3_kernel(
    const float* r0, const float* g0, const float* b0, float* sc0, float* sh0,
    const float* r1, const float* g1, const float* b1, float* sc1, float* sh1,
    const float* r2, const float* g2, const float* b2, float* sc2, float* sh2)
{
    int stage = blockIdx.x >> 5;
    int c4 = (blockIdx.x & 31) * 4;
    if (stage == 0)      stats_body(r0, g0, b0, sc0, sh0, c4);
    else if (stage == 1) stats_body(r1, g1, b1, sc1, sh1, c4);
    else                 stats_body(r2, g2, b2, sc2, sh2, c4);
}

// ================= launcher ======================================================
extern "C" void kernel_launch(void* const* d_in, const int* in_sizes, int n_in,
                              void* d_out, int out_size)
{
    const float* verts   = (const float*)d_in[0];
    const float* dirs_l  = (const float*)d_in[1];
    const float* dirs_m0 = (const float*)d_in[2];
    const float* W_m1    = (const float*)d_in[3];
    const float* b_m1    = (const float*)d_in[4];
    const float* dirs_m1 = (const float*)d_in[5];
    const float* dirs_g0 = (const float*)d_in[6];
    const float* W_g1    = (const float*)d_in[7];
    const float* b_g1    = (const float*)d_in[8];
    const float* dirs_g1 = (const float*)d_in[9];
    const float* W_g2    = (const float*)d_in[10];
    const float* b_g2    = (const float*)d_in[11];
    const float* dirs_g2 = (const float*)d_in[12];
    const float* g_l   = (const float*)d_in[13];
    const float* be_l  = (const float*)d_in[14];
    const float* g_m0  = (const float*)d_in[15];
    const float* be_m0 = (const float*)d_in[16];
    const float* g_m1  = (const float*)d_in[17];
    const float* be_m1 = (const float*)d_in[18];
    const float* g_g0  = (const float*)d_in[19];
    const float* be_g0 = (const float*)d_in[20];
    const float* g_g1  = (const float*)d_in[21];
    const float* be_g1 = (const float*)d_in[22];
    const float* g_g2  = (const float*)d_in[23];
    const float* be_g2 = (const float*)d_in[24];
    const float* W_down = (const float*)d_in[25];
    const float* b_down = (const float*)d_in[26];
    float* out = (float*)d_out;

    float4* nd;    cudaGetSymbolAddress((void**)&nd,    g_nd);
    float*  raw;   cudaGetSymbolAddress((void**)&raw,   g_raw);
    float*  fc_m;  cudaGetSymbolAddress((void**)&fc_m,  g_fc_m);
    float*  fs_m;  cudaGetSymbolAddress((void**)&fs_m,  g_fs_m);
    float*  fc_g;  cudaGetSymbolAddress((void**)&fc_g,  g_fc_g);
    float*  fs_g;  cudaGetSymbolAddress((void**)&fs_g,  g_fs_g);
    float*  scale; cudaGetSymbolAddress((void**)&scale, g_scale);
    float*  shift; cudaGetSymbolAddress((void**)&shift, g_shift);

#define RAW(s) (raw + (size_t)(s)*TOTAL*DCH)
#define SC(s)  (scale + (s)*DCH)
#define SH(s)  (shift + (s)*DCH)

    // 1) KNN + all three surface convs
    knn_surf_kernel<<<TOTAL/8, 256>>>(verts, nd, RAW(0), RAW(1), RAW(3),
                                      dirs_l, dirs_m0, dirs_g0);
    // 2) BN stats for l, m0, g0
    stats3_kernel<<<96, 256>>>(RAW(0), g_l,  be_l,  SC(0), SH(0),
                               RAW(1), g_m0, be_m0, SC(1), SH(1),
                               RAW(3), g_g0, be_g0, SC(3), SH(3));
    // 3) fm@W for medium and global-1 in one grid
    gemm_dual_kernel<<<512, 256>>>(RAW(1), SC(1), SH(1), W_m1, b_m1, fc_m, fs_m,
                                   RAW(3), SC(3), SH(3), W_g1, b_g1, fc_g, fs_g);
    // 4) layer convs m (K=20) and g1 (K=100) in one grid
    conv_dual_kernel<<<1024, 256>>>(nd, dirs_m1, fc_m, fs_m, RAW(2),
                                        dirs_g1, fc_g, fs_g, RAW(4));
    // 5) BN stats m1 + g1
    stats2_kernel<<<64, 256>>>(RAW(2), g_m1, be_m1, SC(2), SH(2),
                               RAW(4), g_g1, be_g1, SC(4), SH(4));
    // 6) global-2 fm@W
    gemm_split_kernel<<<256, 256>>>(RAW(4), SC(4), SH(4), W_g2, b_g2, fc_g, fs_g);
    // 7) global-2 layer conv (K=100)
    conv_single_kernel<<<512, 256>>>(nd, dirs_g2, fc_g, fs_g, RAW(5));
    // 8) BN stats g2
    stats1_kernel<<<32, 256>>>(RAW(5), g_g2, be_g2, SC(5), SH(5));
    // 9) concat + down projection + relu
    gemm_final_kernel<<<256, 256>>>(RAW(0), SC(0), SH(0),
                                    RAW(2), SC(2), SH(2),
                                    RAW(5), SC(5), SH(5),
                                    W_down, b_down, out);
#undef RAW
#undef SC
#undef SH
}

// round 4
// speedup vs baseline: 1.4560x; 1.0884x over previous
#include <cuda_runtime.h>
#include <math.h>
#include <float.h>

#define NPTS   1024
#define BATCH  4
#define TOTAL  (BATCH*NPTS)      // 4096
#define DCH    128
#define KMAX   100

// ---------------- scratch (static device globals; no allocation) ----------------
__device__ float4 g_nd[TOTAL*KMAX];          // normalized edge dirs + idx in .w
__device__ float  g_raw[6][TOTAL*DCH];       // raw (pre-BN) features per stage
__device__ float  g_fc_m[TOTAL*DCH];
__device__ float  g_fs_m[TOTAL*DCH];
__device__ float  g_fc_g[TOTAL*DCH];
__device__ float  g_fs_g[TOTAL*DCH];
__device__ float  g_scale[6*DCH];
__device__ float  g_shift[6*DCH];

// ---------------- f32x2 helpers -------------------------------------------------
__device__ __forceinline__ unsigned long long pack2(float a, float b) {
    unsigned long long r;
    asm("mov.b64 %0, {%1, %2};" : "=l"(r) : "f"(a), "f"(b));
    return r;
}
__device__ __forceinline__ void unpack2(unsigned long long v, float &a, float &b) {
    asm("mov.b64 {%0, %1}, %2;" : "=f"(a), "=f"(b) : "l"(v));
}
__device__ __forceinline__ void ffma2(unsigned long long &d, unsigned long long a, unsigned long long b) {
    asm("fma.rn.f32x2 %0, %1, %2, %3;" : "=l"(d) : "l"(a), "l"(b), "l"(d));
}

// ================= KNN + fused surface convs =====================================
// 4 warps/block, warp per point. Selection loop records winner indices only;
// nd emit + surface convs run as a parallel post-pass.
__global__ __launch_bounds__(128) void knn_surf_kernel(
    const float* __restrict__ verts, float4* __restrict__ nd,
    float* __restrict__ raw_l, float* __restrict__ raw_m, float* __restrict__ raw_g,
    const float* __restrict__ dl, const float* __restrict__ dm, const float* __restrict__ dg)
{
    __shared__ float vx[NPTS], vy[NPTS], vz[NPTS];
    __shared__ unsigned int dk[4][NPTS];
    __shared__ int win_s[4][104];

    int tid = threadIdx.x;
    int p0  = blockIdx.x * 4;
    int b   = p0 >> 10;
    const float* vb = verts + b*NPTS*3;

    for (int t = tid; t < NPTS; t += 128) {
        vx[t] = vb[3*t+0]; vy[t] = vb[3*t+1]; vz[t] = vb[3*t+2];
    }
    __syncthreads();

    int warp = tid >> 5, lane = tid & 31;
    int p = p0 + warp;
    int i = p & (NPTS-1);
    float xi = vx[i], yi = vy[i], zi = vz[i];
    float sqi = xi*xi + yi*yi + zi*zi;

    unsigned int* dw = dk[warp];           // lane-private region [lane*32, lane*32+32)
    int jbase = lane * 32;

    unsigned long long gk0 = ~0ull, gk1 = ~0ull, gk2 = ~0ull, gk3 = ~0ull;
#pragma unroll
    for (int s = 0; s < 32; s++) {
        int j = jbase + s;
        float xj = vx[j], yj = vy[j], zj = vz[j];
        float sqj = xj*xj + yj*yj + zj*zj;
        float dot = xi*xj + yi*yj + zi*zj;
        float d   = sqi + sqj - 2.0f*dot;                    // same formula as reference
        unsigned int bits = __float_as_uint(d);
        unsigned int key  = (bits & 0x80000000u) ? ~bits : (bits | 0x80000000u);
        dw[j] = key;
        unsigned long long k64 = ((unsigned long long)key << 10) | (unsigned)j;
        if ((s>>3) == 0) gk0 = k64 < gk0 ? k64 : gk0;
        if ((s>>3) == 1) gk1 = k64 < gk1 ? k64 : gk1;
        if ((s>>3) == 2) gk2 = k64 < gk2 ? k64 : gk2;
        if ((s>>3) == 3) gk3 = k64 < gk3 ? k64 : gk3;
    }
    {
        unsigned long long a01 = gk0 < gk1 ? gk0 : gk1;
        unsigned long long a23 = gk2 < gk3 ? gk2 : gk3;
        unsigned long long bk  = a01 < a23 ? a01 : a23;

        // selection loop: 101 picks, 32-bit reduce + ballot tie-break
        for (int t = 0; t <= KMAX; t++) {
            unsigned int key = (unsigned int)(bk >> 10);
            unsigned int m = key;
#pragma unroll
            for (int off = 16; off; off >>= 1) {
                unsigned int m2 = __shfl_xor_sync(0xffffffffu, m, off);
                m = m2 < m ? m2 : m;
            }
            // lane order == index order, so lowest tied lane owns lowest index
            unsigned int mask = __ballot_sync(0xffffffffu, key == m);
            int src = __ffs(mask) - 1;
            unsigned long long wk = __shfl_sync(0xffffffffu, bk, src);
            int w = (int)(wk & 1023u);

            if (lane == src) {
                win_s[warp][t] = w;
                dw[w] = 0xFFFFFFFFu;
                int g = (w >> 3) & 3;
                int base = jbase + g*8;
                unsigned long long ng = ~0ull;
#pragma unroll
                for (int s = 0; s < 8; s++) {
                    int j = base + s;
                    unsigned long long k64 = ((unsigned long long)dw[j] << 10) | (unsigned)j;
                    ng = k64 < ng ? k64 : ng;
                }
                if (g == 0) gk0 = ng; else if (g == 1) gk1 = ng;
                else if (g == 2) gk2 = ng; else gk3 = ng;
                unsigned long long m01 = gk0 < gk1 ? gk0 : gk1;
                unsigned long long m23 = gk2 < gk3 ? gk2 : gk3;
                bk = m01 < m23 ? m01 : m23;
            }
        }
    }
    __syncwarp();

    // -------- post-pass: nd emit + fused surface convs --------
    int col0 = lane*4;
    float l0[4], l1[4], l2[4], m0[4], m1[4], m2[4], q0[4], q1[4], q2[4];
#pragma unroll
    for (int c = 0; c < 4; c++) {
        int col = col0 + c;
        float a0, a1, a2, inv;
        a0 = dl[col]; a1 = dl[128+col]; a2 = dl[256+col];
        inv = 1.0f / fmaxf(sqrtf(a0*a0+a1*a1+a2*a2), 1e-12f);
        l0[c]=a0*inv; l1[c]=a1*inv; l2[c]=a2*inv;
        a0 = dm[col]; a1 = dm[128+col]; a2 = dm[256+col];
        inv = 1.0f / fmaxf(sqrtf(a0*a0+a1*a1+a2*a2), 1e-12f);
        m0[c]=a0*inv; m1[c]=a1*inv; m2[c]=a2*inv;
        a0 = dg[col]; a1 = dg[128+col]; a2 = dg[256+col];
        inv = 1.0f / fmaxf(sqrtf(a0*a0+a1*a1+a2*a2), 1e-12f);
        q0[c]=a0*inv; q1[c]=a1*inv; q2[c]=a2*inv;
    }

    float accl[4] = {0,0,0,0}, accm[4] = {0,0,0,0}, accg[4] = {0,0,0,0};
    float4* ndp = nd + (size_t)p*KMAX;

#pragma unroll 2
    for (int t = 1; t <= KMAX; t++) {
        int w = win_s[warp][t];
        float dx = vx[w]-xi, dy = vy[w]-yi, dz = vz[w]-zi;
        float inv = 1.0f / fmaxf(sqrtf(dx*dx + dy*dy + dz*dz), 1e-12f);
        float nx = dx*inv, ny = dy*inv, nz = dz*inv;
        int kk = t-1;
        if (lane == (kk & 31))
            ndp[kk] = make_float4(nx, ny, nz, __int_as_float(w));
#pragma unroll
        for (int c = 0; c < 4; c++)
            accg[c] = fmaxf(accg[c], nx*q0[c] + ny*q1[c] + nz*q2[c]);
        if (kk < 20) {
#pragma unroll
            for (int c = 0; c < 4; c++)
                accm[c] = fmaxf(accm[c], nx*m0[c] + ny*m1[c] + nz*m2[c]);
            if (kk < 5) {
#pragma unroll
                for (int c = 0; c < 4; c++)
                    accl[c] = fmaxf(accl[c], nx*l0[c] + ny*l1[c] + nz*l2[c]);
            }
        }
    }

    *(float4*)&raw_l[(size_t)p*DCH + col0] = make_float4(accl[0],accl[1],accl[2],accl[3]);
    *(float4*)&raw_m[(size_t)p*DCH + col0] = make_float4(accm[0],accm[1],accm[2],accm[3]);
    *(float4*)&raw_g[(size_t)p*DCH + col0] = make_float4(accg[0],accg[1],accg[2],accg[3]);
}

// ================= GEMM core: 16 rows x 256 cols, k-pair f32x2 ===================
struct GemmSmem { unsigned long long in_s[16][65]; };

template<bool RELU>
__device__ __forceinline__ void gemm16_body(
    GemmSmem* sm,
    const float* __restrict__ A, const float* __restrict__ sc, const float* __restrict__ sh,
    const float* __restrict__ W, const float* __restrict__ bias,
    float* __restrict__ outc, float* __restrict__ outs, int r0)
{
    int tid = threadIdx.x;
#pragma unroll
    for (int it = 0; it < 8; it++) {
        int idx = tid + it*256;
        int r = idx >> 7, k = idx & 127;
        float x = A[(size_t)(r0+r)*DCH + k];
        float val = fmaxf(fmaf(x, sc[k], sh[k]), 0.f);
        ((float*)&sm->in_s[r][k>>1])[k&1] = val;
    }
    __syncthreads();

    int col0 = (tid & 63) * 4;
    int rg   = tid >> 6;
    const unsigned long long* A0 = sm->in_s[rg*4+0];
    const unsigned long long* A1 = sm->in_s[rg*4+1];
    const unsigned long long* A2 = sm->in_s[rg*4+2];
    const unsigned long long* A3 = sm->in_s[rg*4+3];

    unsigned long long acc[4][4];
#pragma unroll
    for (int c = 0; c < 4; c++)
#pragma unroll
        for (int r = 0; r < 4; r++) acc[c][r] = 0ull;

    float4 wa = *(const float4*)(W + 0*256 + col0);
    float4 wb = *(const float4*)(W + 1*256 + col0);

#pragma unroll 4
    for (int pk = 0; pk < 64; pk++) {
        int np = pk < 63 ? pk + 1 : 63;
        float4 wan = *(const float4*)(W + (2*np+0)*256 + col0);
        float4 wbn = *(const float4*)(W + (2*np+1)*256 + col0);

        unsigned long long w0 = pack2(wa.x, wb.x);
        unsigned long long w1 = pack2(wa.y, wb.y);
        unsigned long long w2 = pack2(wa.z, wb.z);
        unsigned long long w3 = pack2(wa.w, wb.w);
        unsigned long long a0 = A0[pk], a1 = A1[pk], a2 = A2[pk], a3 = A3[pk];

        ffma2(acc[0][0], a0, w0); ffma2(acc[0][1], a1, w0);
        ffma2(acc[0][2], a2, w0); ffma2(acc[0][3], a3, w0);
        ffma2(acc[1][0], a0, w1); ffma2(acc[1][1], a1, w1);
        ffma2(acc[1][2], a2, w1); ffma2(acc[1][3], a3, w1);
        ffma2(acc[2][0], a0, w2); ffma2(acc[2][1], a1, w2);
        ffma2(acc[2][2], a2, w2); ffma2(acc[2][3], a3, w2);
        ffma2(acc[3][0], a0, w3); ffma2(acc[3][1], a1, w3);
        ffma2(acc[3][2], a2, w3); ffma2(acc[3][3], a3, w3);

        wa = wan; wb = wbn;
    }

    float4 bb = *(const float4*)(bias + col0);
    float* dst; int cbase;
    if (outs && col0 >= 128) { dst = outs; cbase = col0 - 128; }
    else                     { dst = outc; cbase = col0; }
    int stride = outs ? DCH : 256;

#pragma unroll
    for (int r = 0; r < 4; r++) {
        float v0, v1, v2, v3, lo, hi;
        unpack2(acc[0][r], lo, hi); v0 = lo + hi + bb.x;
        unpack2(acc[1][r], lo, hi); v1 = lo + hi + bb.y;
        unpack2(acc[2][r], lo, hi); v2 = lo + hi + bb.z;
        unpack2(acc[3][r], lo, hi); v3 = lo + hi + bb.w;
        if (RELU) { v0=fmaxf(v0,0.f); v1=fmaxf(v1,0.f); v2=fmaxf(v2,0.f); v3=fmaxf(v3,0.f); }
        int row = r0 + rg*4 + r;
        *(float4*)&dst[(size_t)row*stride + cbase] = make_float4(v0,v1,v2,v3);
    }
}

__global__ __launch_bounds__(256) void gemm_split_kernel(
    const float* A, const float* sc, const float* sh,
    const float* W, const float* bias, float* fc, float* fs)
{
    __shared__ GemmSmem sm;
    gemm16_body<false>(&sm, A, sc, sh, W, bias, fc, fs, blockIdx.x*16);
}

__global__ __launch_bounds__(256) void gemm_dual_kernel(
    const float* A0, const float* sc0, const float* sh0, const float* W0, const float* b0,
    float* fc0, float* fs0,
    const float* A1, const float* sc1, const float* sh1, const float* W1, const float* b1,
    float* fc1, float* fs1)
{
    __shared__ GemmSmem sm;
    int bid = blockIdx.x;
    if (bid < 256) gemm16_body<false>(&sm, A0, sc0, sh0, W0, b0, fc0, fs0, bid*16);
    else           gemm16_body<false>(&sm, A1, sc1, sh1, W1, b1, fc1, fs1, (bid-256)*16);
}

// ---------------- final GEMM: K=384 (3 BN'd sources), relu ----------------------
__global__ __launch_bounds__(256) void gemm_final_kernel(
    const float* __restrict__ rl, const float* __restrict__ scl, const float* __restrict__ shl,
    const float* __restrict__ rm, const float* __restrict__ scm, const float* __restrict__ shm,
    const float* __restrict__ rg, const float* __restrict__ scg, const float* __restrict__ shg,
    const float* __restrict__ Wd, const float* __restrict__ bd, float* __restrict__ out)
{
    __shared__ unsigned long long in_s[16][193];
    int tid = threadIdx.x;
    int r0 = blockIdx.x * 16;

    const float* srcs[3] = {rl, rm, rg};
    const float* scs[3]  = {scl, scm, scg};
    const float* shs[3]  = {shl, shm, shg};
#pragma unroll
    for (int s = 0; s < 3; s++) {
        const float* A = srcs[s]; const float* sc = scs[s]; const float* sh = shs[s];
#pragma unroll
        for (int it = 0; it < 8; it++) {
            int idx = tid + it*256;
            int r = idx >> 7, k = idx & 127;
            float x = A[(size_t)(r0+r)*DCH + k];
            float val = fmaxf(fmaf(x, sc[k], sh[k]), 0.f);
            ((float*)&in_s[r][64*s + (k>>1)])[k&1] = val;
        }
    }
    __syncthreads();

    int col0 = (tid & 63) * 4;
    int rg_  = tid >> 6;
    const unsigned long long* A0 = in_s[rg_*4+0];
    const unsigned long long* A1 = in_s[rg_*4+1];
    const unsigned long long* A2 = in_s[rg_*4+2];
    const unsigned long long* A3 = in_s[rg_*4+3];

    unsigned long long acc[4][4];
#pragma unroll
    for (int c = 0; c < 4; c++)
#pragma unroll
        for (int r = 0; r < 4; r++) acc[c][r] = 0ull;

    float4 wa = *(const float4*)(Wd + 0*256 + col0);
    float4 wb = *(const float4*)(Wd + 1*256 + col0);

#pragma unroll 4
    for (int pk = 0; pk < 192; pk++) {
        int np = pk < 191 ? pk + 1 : 191;
        float4 wan = *(const float4*)(Wd + (2*np+0)*256 + col0);
        float4 wbn = *(const float4*)(Wd + (2*np+1)*256 + col0);

        unsigned long long w0 = pack2(wa.x, wb.x);
        unsigned long long w1 = pack2(wa.y, wb.y);
        unsigned long long w2 = pack2(wa.z, wb.z);
        unsigned long long w3 = pack2(wa.w, wb.w);
        unsigned long long a0 = A0[pk], a1 = A1[pk], a2 = A2[pk], a3 = A3[pk];

        ffma2(acc[0][0], a0, w0); ffma2(acc[0][1], a1, w0);
        ffma2(acc[0][2], a2, w0); ffma2(acc[0][3], a3, w0);
        ffma2(acc[1][0], a0, w1); ffma2(acc[1][1], a1, w1);
        ffma2(acc[1][2], a2, w1); ffma2(acc[1][3], a3, w1);
        ffma2(acc[2][0], a0, w2); ffma2(acc[2][1], a1, w2);
        ffma2(acc[2][2], a2, w2); ffma2(acc[2][3], a3, w2);
        ffma2(acc[3][0], a0, w3); ffma2(acc[3][1], a1, w3);
        ffma2(acc[3][2], a2, w3); ffma2(acc[3][3], a3, w3);

        wa = wan; wb = wbn;
    }

    float4 bb = *(const float4*)(bd + col0);
#pragma unroll
    for (int r = 0; r < 4; r++) {
        float v0, v1, v2, v3, lo, hi;
        unpack2(acc[0][r], lo, hi); v0 = fmaxf(lo + hi + bb.x, 0.f);
        unpack2(acc[1][r], lo, hi); v1 = fmaxf(lo + hi + bb.y, 0.f);
        unpack2(acc[2][r], lo, hi); v2 = fmaxf(lo + hi + bb.z, 0.f);
        unpack2(acc[3][r], lo, hi); v3 = fmaxf(lo + hi + bb.w, 0.f);
        int row = r0 + rg_*4 + r;
        *(float4*)&out[(size_t)row*256 + col0] = make_float4(v0,v1,v2,v3);
    }
}

// ================= layer conv ====================================================
__device__ __forceinline__ void conv_body(
    const float4* __restrict__ nd, const float* __restrict__ dirs,
    const float* __restrict__ fc, const float* __restrict__ fs,
    float* __restrict__ raw, int K, int p)
{
    int lane = threadIdx.x & 31;
    int rowbase = p & ~(NPTS-1);
    int col0 = lane*4;

    float d0[4], d1[4], d2[4];
#pragma unroll
    for (int c = 0; c < 4; c++) {
        int col = col0 + c;
        float a0 = dirs[col], a1 = dirs[128+col], a2 = dirs[256+col];
        float inv = 1.0f / fmaxf(sqrtf(a0*a0+a1*a1+a2*a2), 1e-12f);
        d0[c]=a0*inv; d1[c]=a1*inv; d2[c]=a2*inv;
    }

    float acc[4] = {-FLT_MAX, -FLT_MAX, -FLT_MAX, -FLT_MAX};
    const float4* ndp = nd + (size_t)p*KMAX;

#pragma unroll 8
    for (int kk = 0; kk < K; kk++) {
        float4 v = ndp[kk];
        int j = __float_as_int(v.w);
        float4 f = *(const float4*)(fs + (size_t)(rowbase + j)*DCH + col0);
        float t0 = fmaxf(v.x*d0[0] + v.y*d1[0] + v.z*d2[0], 0.0f);
        float t1 = fmaxf(v.x*d0[1] + v.y*d1[1] + v.z*d2[1], 0.0f);
        float t2 = fmaxf(v.x*d0[2] + v.y*d1[2] + v.z*d2[2], 0.0f);
        float t3 = fmaxf(v.x*d0[3] + v.y*d1[3] + v.z*d2[3], 0.0f);
        acc[0] = fmaxf(acc[0], t0*f.x);
        acc[1] = fmaxf(acc[1], t1*f.y);
        acc[2] = fmaxf(acc[2], t2*f.z);
        acc[3] = fmaxf(acc[3], t3*f.w);
    }

    float4 c4 = *(const float4*)(fc + (size_t)p*DCH + col0);
    *(float4*)&raw[(size_t)p*DCH + col0] =
        make_float4(c4.x + acc[0], c4.y + acc[1], c4.z + acc[2], c4.w + acc[3]);
}

__global__ __launch_bounds__(256) void conv_dual_kernel(
    const float4* nd,
    const float* dirs_m, const float* fc_m, const float* fs_m, float* raw_m,
    const float* dirs_g, const float* fc_g, const float* fs_g, float* raw_g)
{
    int bid = blockIdx.x, warp = threadIdx.x >> 5;
    if (bid < 512) conv_body(nd, dirs_m, fc_m, fs_m, raw_m, 20,  bid*8 + warp);
    else           conv_body(nd, dirs_g, fc_g, fs_g, raw_g, 100, (bid-512)*8 + warp);
}

__global__ __launch_bounds__(256) void conv_single_kernel(
    const float4* nd, const float* dirs, const float* fc, const float* fs, float* raw)
{
    conv_body(nd, dirs, fc, fs, raw, 100, blockIdx.x*8 + (threadIdx.x >> 5));
}

// ================= BN stats ======================================================
__device__ __forceinline__ void stats_body(const float* __restrict__ raw,
                                           const float* __restrict__ g,
                                           const float* __restrict__ be,
                                           float* __restrict__ scale,
                                           float* __restrict__ shift, int c4)
{
    int tid = threadIdx.x;
    float s0=0,s1=0,s2=0,s3=0,q0=0,q1=0,q2=0,q3=0;
    for (int r = tid; r < TOTAL; r += 256) {
        float4 v = *(const float4*)(raw + (size_t)r*DCH + c4);
        s0 += v.x; q0 += v.x*v.x;
        s1 += v.y; q1 += v.y*v.y;
        s2 += v.z; q2 += v.z*v.z;
        s3 += v.w; q3 += v.w*v.w;
    }
#pragma unroll
    for (int off = 16; off; off >>= 1) {
        s0 += __shfl_xor_sync(0xffffffffu, s0, off);
        s1 += __shfl_xor_sync(0xffffffffu, s1, off);
        s2 += __shfl_xor_sync(0xffffffffu, s2, off);
        s3 += __shfl_xor_sync(0xffffffffu, s3, off);
        q0 += __shfl_xor_sync(0xffffffffu, q0, off);
        q1 += __shfl_xor_sync(0xffffffffu, q1, off);
        q2 += __shfl_xor_sync(0xffffffffu, q2, off);
        q3 += __shfl_xor_sync(0xffffffffu, q3, off);
    }
    __shared__ float red[8][8];
    int warp = tid >> 5, lane = tid & 31;
    if (lane == 0) {
        red[warp][0]=s0; red[warp][1]=s1; red[warp][2]=s2; red[warp][3]=s3;
        red[warp][4]=q0; red[warp][5]=q1; red[warp][6]=q2; red[warp][7]=q3;
    }
    __syncthreads();
    if (tid < 8) {
        float t = 0.f;
#pragma unroll
        for (int w = 0; w < 8; w++) t += red[w][tid];
        red[0][tid] = t;
    }
    __syncthreads();
    if (tid < 4) {
        float mean = red[0][tid] * (1.0f/TOTAL);
        float var  = fmaxf(red[0][4+tid] * (1.0f/TOTAL) - mean*mean, 0.f);
        float sc   = g[c4+tid] * rsqrtf(var + 1e-5f);
        scale[c4+tid] = sc;
        shift[c4+tid] = be[c4+tid] - mean*sc;
    }
}

__global__ __launch_bounds__(256) void stats1_kernel(const float* raw, const float* g,
                                                     const float* be, float* scale, float* shift)
{
    stats_body(raw, g, be, scale, shift, blockIdx.x*4);
}

__global__ __launch_bounds__(256) void stats2_kernel(
    const float* r0, const float* g0, const float* b0, float* sc0, float* sh0,
    const float* r1, const float* g1, const float* b1, float* sc1, float* sh1)
{
    int stage = blockIdx.x >> 5;
    int c4 = (blockIdx.x & 31) * 4;
    if (stage == 0) stats_body(r0, g0, b0, sc0, sh0, c4);
    else            stats_body(r1, g1, b1, sc1, sh1, c4);
}

__global__ __launch_bounds__(256) void stats3_kernel(
    const float* r0, const float* g0, const float* b0, float* sc0, float* sh0,
    const float* r1, const float* g1, const float* b1, float* sc1, float* sh1,
    const float* r2, const float* g2, const float* b2, float* sc2, float* sh2)
{
    int stage = blockIdx.x >> 5;
    int c4 = (blockIdx.x & 31) * 4;
    if (stage == 0)      stats_body(r0, g0, b0, sc0, sh0, c4);
    else if (stage == 1) stats_body(r1, g1, b1, sc1, sh1, c4);
    else                 stats_body(r2, g2, b2, sc2, sh2, c4);
}

// ================= launcher ======================================================
extern "C" void kernel_launch(void* const* d_in, const int* in_sizes, int n_in,
                              void* d_out, int out_size)
{
    const float* verts   = (const float*)d_in[0];
    const float* dirs_l  = (const float*)d_in[1];
    const float* dirs_m0 = (const float*)d_in[2];
    const float* W_m1    = (const float*)d_in[3];
    const float* b_m1    = (const float*)d_in[4];
    const float* dirs_m1 = (const float*)d_in[5];
    const float* dirs_g0 = (const float*)d_in[6];
    const float* W_g1    = (const float*)d_in[7];
    const float* b_g1    = (const float*)d_in[8];
    const float* dirs_g1 = (const float*)d_in[9];
    const float* W_g2    = (const float*)d_in[10];
    const float* b_g2    = (const float*)d_in[11];
    const float* dirs_g2 = (const float*)d_in[12];
    const float* g_l   = (const float*)d_in[13];
    const float* be_l  = (const float*)d_in[14];
    const float* g_m0  = (const float*)d_in[15];
    const float* be_m0 = (const float*)d_in[16];
    const float* g_m1  = (const float*)d_in[17];
    const float* be_m1 = (const float*)d_in[18];
    const float* g_g0  = (const float*)d_in[19];
    const float* be_g0 = (const float*)d_in[20];
    const float* g_g1  = (const float*)d_in[21];
    const float* be_g1 = (const float*)d_in[22];
    const float* g_g2  = (const float*)d_in[23];
    const float* be_g2 = (const float*)d_in[24];
    const float* W_down = (const float*)d_in[25];
    const float* b_down = (const float*)d_in[26];
    float* out = (float*)d_out;

    float4* nd;    cudaGetSymbolAddress((void**)&nd,    g_nd);
    float*  raw;   cudaGetSymbolAddress((void**)&raw,   g_raw);
    float*  fc_m;  cudaGetSymbolAddress((void**)&fc_m,  g_fc_m);
    float*  fs_m;  cudaGetSymbolAddress((void**)&fs_m,  g_fs_m);
    float*  fc_g;  cudaGetSymbolAddress((void**)&fc_g,  g_fc_g);
    float*  fs_g;  cudaGetSymbolAddress((void**)&fs_g,  g_fs_g);
    float*  scale; cudaGetSymbolAddress((void**)&scale, g_scale);
    float*  shift; cudaGetSymbolAddress((void**)&shift, g_shift);

#define RAW(s) (raw + (size_t)(s)*TOTAL*DCH)
#define SC(s)  (scale + (s)*DCH)
#define SH(s)  (shift + (s)*DCH)

    // 1) KNN + all three surface convs (4 warps/block for occupancy)
    knn_surf_kernel<<<TOTAL/4, 128>>>(verts, nd, RAW(0), RAW(1), RAW(3),
                                      dirs_l, dirs_m0, dirs_g0);
    // 2) BN stats for l, m0, g0
    stats3_kernel<<<96, 256>>>(RAW(0), g_l,  be_l,  SC(0), SH(0),
                               RAW(1), g_m0, be_m0, SC(1), SH(1),
                               RAW(3), g_g0, be_g0, SC(3), SH(3));
    // 3) fm@W for medium and global-1 in one grid
    gemm_dual_kernel<<<512, 256>>>(RAW(1), SC(1), SH(1), W_m1, b_m1, fc_m, fs_m,
                                   RAW(3), SC(3), SH(3), W_g1, b_g1, fc_g, fs_g);
    // 4) layer convs m (K=20) and g1 (K=100) in one grid
    conv_dual_kernel<<<1024, 256>>>(nd, dirs_m1, fc_m, fs_m, RAW(2),
                                        dirs_g1, fc_g, fs_g, RAW(4));
    // 5) BN stats m1 + g1
    stats2_kernel<<<64, 256>>>(RAW(2), g_m1, be_m1, SC(2), SH(2),
                               RAW(4), g_g1, be_g1, SC(4), SH(4));
    // 6) global-2 fm@W
    gemm_split_kernel<<<256, 256>>>(RAW(4), SC(4), SH(4), W_g2, b_g2, fc_g, fs_g);
    // 7) global-2 layer conv (K=100)
    conv_single_kernel<<<512, 256>>>(nd, dirs_g2, fc_g, fs_g, RAW(5));
    // 8) BN stats g2
    stats1_kernel<<<32, 256>>>(RAW(5), g_g2, be_g2, SC(5), SH(5));
    // 9) concat + down projection + relu
    gemm_final_kernel<<<256, 256>>>(RAW(0), SC(0), SH(0),
                                    RAW(2), SC(2), SH(2),
                                    RAW(5), SC(5), SH(5),
                                    W_down, b_down, out);
#undef RAW
#undef SC
#undef SH
}

// round 5
// speedup vs baseline: 2.2468x; 1.5431x over previous
#include <cuda_runtime.h>
#include <math.h>
#include <float.h>

#define NPTS   1024
#define BATCH  4
#define TOTAL  (BATCH*NPTS)      // 4096
#define DCH    128
#define KMAX   100

// ---------------- scratch (static device globals; no allocation) ----------------
__device__ float4 g_nd[TOTAL*KMAX];          // normalized edge dirs + idx in .w (sorted)
__device__ float  g_raw[6][TOTAL*DCH];       // raw (pre-BN) features per stage
__device__ float  g_fc_m[TOTAL*DCH];
__device__ float  g_fs_m[TOTAL*DCH];
__device__ float  g_fc_g[TOTAL*DCH];
__device__ float  g_fs_g[TOTAL*DCH];
__device__ float  g_scale[6*DCH];
__device__ float  g_shift[6*DCH];

// ---------------- f32x2 helpers -------------------------------------------------
__device__ __forceinline__ unsigned long long pack2(float a, float b) {
    unsigned long long r;
    asm("mov.b64 %0, {%1, %2};" : "=l"(r) : "f"(a), "f"(b));
    return r;
}
__device__ __forceinline__ void unpack2(unsigned long long v, float &a, float &b) {
    asm("mov.b64 {%0, %1}, %2;" : "=f"(a), "=f"(b) : "l"(v));
}
__device__ __forceinline__ void ffma2(unsigned long long &d, unsigned long long a, unsigned long long b) {
    asm("fma.rn.f32x2 %0, %1, %2, %3;" : "=l"(d) : "l"(a), "l"(b), "l"(d));
}

// ================= KNN (block-per-point exact rank select) + surface convs ======
__global__ __launch_bounds__(128) void knn_surf_kernel(
    const float* __restrict__ verts, float4* __restrict__ nd,
    float* __restrict__ raw_l, float* __restrict__ raw_m, float* __restrict__ raw_g,
    const float* __restrict__ dl, const float* __restrict__ dm, const float* __restrict__ dg)
{
    __shared__ float vx[NPTS], vy[NPTS], vz[NPTS];
    __shared__ unsigned int hist[2176];                   // 2048 buckets, padded b+(b>>4)
    __shared__ unsigned long long list_s[NPTS];
    __shared__ unsigned long long sel_s[104];
    __shared__ float ndx_s[100], ndy_s[100], ndz_s[100];
    __shared__ float gacc_s[4][128];
    __shared__ unsigned int chunk_s[128];
    __shared__ unsigned int wtot[4];
    __shared__ unsigned int cnt_s, selcnt_s, B_s, q_s;
    __shared__ unsigned long long T100_s;

    int tid = threadIdx.x;
    int p = blockIdx.x;
    int b = p >> 10;
    int i = p & (NPTS-1);
    const float* vb = verts + b*NPTS*3;

    for (int t = tid; t < NPTS; t += 128) {
        vx[t] = vb[3*t+0]; vy[t] = vb[3*t+1]; vz[t] = vb[3*t+2];
    }
    for (int t = tid; t < 2176; t += 128) hist[t] = 0;
    if (tid == 0) { cnt_s = 0; selcnt_s = 0; }
    __syncthreads();

    float xi = vx[i], yi = vy[i], zi = vz[i];
    float sqi = xi*xi + yi*yi + zi*zi;

    unsigned long long k64[8];
#pragma unroll
    for (int s = 0; s < 8; s++) {
        int j = tid + s*128;
        float xj = vx[j], yj = vy[j], zj = vz[j];
        float sqj = xj*xj + yj*yj + zj*zj;
        float dot = xi*xj + yi*yj + zi*zj;
        float d   = sqi + sqj - 2.0f*dot;                 // same formula as reference
        unsigned int bits = __float_as_uint(d);
        unsigned int key  = (bits & 0x80000000u) ? ~bits : (bits | 0x80000000u);
        k64[s] = ((unsigned long long)key << 10) | (unsigned)j;
        unsigned int bu = key >> 21;
        atomicAdd(&hist[bu + (bu>>4)], 1u);
    }
    __syncthreads();

    // ---- block scan of 2048 bucket counts (chunk of 16 per thread) ----
    int base = tid*16;
    unsigned int run = 0;
#pragma unroll
    for (int t = 0; t < 16; t++) run += hist[base + t + tid];   // padded: conflict-free
    chunk_s[tid] = run;
    __syncthreads();

    int lane = tid & 31, warp = tid >> 5;
    unsigned int xv = chunk_s[tid];
    unsigned int inc = xv;
#pragma unroll
    for (int off = 1; off < 32; off <<= 1) {
        unsigned int y = __shfl_up_sync(0xffffffffu, inc, off);
        if (lane >= off) inc += y;
    }
    if (lane == 31) wtot[warp] = inc;
    __syncthreads();
    unsigned int wbase = 0;
    for (int w = 0; w < warp; w++) wbase += wtot[w];
    unsigned int chunk_base = wbase + inc - xv;            // exclusive prefix of my chunk

    // ---- locate bucket holding global rank 100 ----
    {
        unsigned int pr = chunk_base;
#pragma unroll
        for (int t = 0; t < 16; t++) {
            unsigned int c = hist[base + t + tid];
            if (pr <= 100u && 100u < pr + c) { B_s = (unsigned)(base + t); q_s = 100u - pr; }
            pr += c;
        }
    }
    __syncthreads();

    unsigned int B = B_s, q = q_s;
    // ---- collect that bucket's elements ----
#pragma unroll
    for (int s = 0; s < 8; s++) {
        unsigned int bu = (unsigned int)(k64[s] >> 31);    // (key>>21)
        if (bu == B) { unsigned int idx = atomicAdd(&cnt_s, 1u); list_s[idx] = k64[s]; }
    }
    __syncthreads();
    unsigned int cnt = cnt_s;
    for (unsigned int ii = tid; ii < cnt; ii += 128) {
        unsigned long long me = list_s[ii];
        unsigned int r = 0;
        for (unsigned int j2 = 0; j2 < cnt; j2++) r += (list_s[j2] < me) ? 1u : 0u;
        if (r == q) T100_s = me;
    }
    __syncthreads();
    unsigned long long T = T100_s;

    // ---- compact the 101 smallest ----
#pragma unroll
    for (int s = 0; s < 8; s++) {
        if (k64[s] <= T) { unsigned int idx = atomicAdd(&selcnt_s, 1u); sel_s[idx] = k64[s]; }
    }
    __syncthreads();

    // ---- rank the 101, emit sorted nd (rank 0 = self-order min dropped) ----
    if (tid < 101) {
        unsigned long long me = sel_s[tid];
        unsigned int r = 0;
#pragma unroll 4
        for (int j2 = 0; j2 < 101; j2++) r += (sel_s[j2] < me) ? 1u : 0u;
        if (r > 0) {
            int slot = (int)r - 1;
            int j = (int)(me & 1023u);
            float dx = vx[j]-xi, dy = vy[j]-yi, dz = vz[j]-zi;
            float inv = 1.0f / fmaxf(sqrtf(dx*dx + dy*dy + dz*dz), 1e-12f);
            float nx = dx*inv, ny = dy*inv, nz = dz*inv;
            ndx_s[slot] = nx; ndy_s[slot] = ny; ndz_s[slot] = nz;
            nd[(size_t)p*KMAX + slot] = make_float4(nx, ny, nz, __int_as_float(j));
        }
    }
    __syncthreads();

    // ---- surface convs: warp w handles slots [w*25, w*25+25), 4 channels/lane ----
    int col0 = lane*4;
    float q0[4], q1[4], q2[4];
#pragma unroll
    for (int c = 0; c < 4; c++) {
        int col = col0 + c;
        float a0 = dg[col], a1 = dg[128+col], a2 = dg[256+col];
        float inv = 1.0f / fmaxf(sqrtf(a0*a0+a1*a1+a2*a2), 1e-12f);
        q0[c]=a0*inv; q1[c]=a1*inv; q2[c]=a2*inv;
    }
    float accg[4] = {0,0,0,0};

    if (warp == 0) {
        float l0[4], l1[4], l2[4], m0[4], m1[4], m2[4];
#pragma unroll
        for (int c = 0; c < 4; c++) {
            int col = col0 + c;
            float a0, a1, a2, inv;
            a0 = dl[col]; a1 = dl[128+col]; a2 = dl[256+col];
            inv = 1.0f / fmaxf(sqrtf(a0*a0+a1*a1+a2*a2), 1e-12f);
            l0[c]=a0*inv; l1[c]=a1*inv; l2[c]=a2*inv;
            a0 = dm[col]; a1 = dm[128+col]; a2 = dm[256+col];
            inv = 1.0f / fmaxf(sqrtf(a0*a0+a1*a1+a2*a2), 1e-12f);
            m0[c]=a0*inv; m1[c]=a1*inv; m2[c]=a2*inv;
        }
        float accl[4] = {0,0,0,0}, accm[4] = {0,0,0,0};
#pragma unroll 1
        for (int s = 0; s < 25; s++) {
            float nx = ndx_s[s], ny = ndy_s[s], nz = ndz_s[s];
#pragma unroll
            for (int c = 0; c < 4; c++)
                accg[c] = fmaxf(accg[c], nx*q0[c] + ny*q1[c] + nz*q2[c]);
            if (s < 20) {
#pragma unroll
                for (int c = 0; c < 4; c++)
                    accm[c] = fmaxf(accm[c], nx*m0[c] + ny*m1[c] + nz*m2[c]);
            }
            if (s < 5) {
#pragma unroll
                for (int c = 0; c < 4; c++)
                    accl[c] = fmaxf(accl[c], nx*l0[c] + ny*l1[c] + nz*l2[c]);
            }
        }
        *(float4*)&raw_l[(size_t)p*DCH + col0] = make_float4(accl[0],accl[1],accl[2],accl[3]);
        *(float4*)&raw_m[(size_t)p*DCH + col0] = make_float4(accm[0],accm[1],accm[2],accm[3]);
    } else {
        int sbeg = warp*25;
#pragma unroll 1
        for (int s = sbeg; s < sbeg + 25; s++) {
            float nx = ndx_s[s], ny = ndy_s[s], nz = ndz_s[s];
#pragma unroll
            for (int c = 0; c < 4; c++)
                accg[c] = fmaxf(accg[c], nx*q0[c] + ny*q1[c] + nz*q2[c]);
        }
    }
    *(float4*)&gacc_s[warp][col0] = make_float4(accg[0],accg[1],accg[2],accg[3]);
    __syncthreads();
    float gm = fmaxf(fmaxf(gacc_s[0][tid], gacc_s[1][tid]),
                     fmaxf(gacc_s[2][tid], gacc_s[3][tid]));
    raw_g[(size_t)p*DCH + tid] = gm;
}

// ================= GEMM core: 16 rows x 256 cols, k-pair f32x2 ===================
struct GemmSmem { unsigned long long in_s[16][65]; };

template<bool RELU>
__device__ __forceinline__ void gemm16_body(
    GemmSmem* sm,
    const float* __restrict__ A, const float* __restrict__ sc, const float* __restrict__ sh,
    const float* __restrict__ W, const float* __restrict__ bias,
    float* __restrict__ outc, float* __restrict__ outs, int r0)
{
    int tid = threadIdx.x;
#pragma unroll
    for (int it = 0; it < 8; it++) {
        int idx = tid + it*256;
        int r = idx >> 7, k = idx & 127;
        float x = A[(size_t)(r0+r)*DCH + k];
        float val = fmaxf(fmaf(x, sc[k], sh[k]), 0.f);
        ((float*)&sm->in_s[r][k>>1])[k&1] = val;
    }
    __syncthreads();

    int col0 = (tid & 63) * 4;
    int rg   = tid >> 6;
    const unsigned long long* A0 = sm->in_s[rg*4+0];
    const unsigned long long* A1 = sm->in_s[rg*4+1];
    const unsigned long long* A2 = sm->in_s[rg*4+2];
    const unsigned long long* A3 = sm->in_s[rg*4+3];

    unsigned long long acc[4][4];
#pragma unroll
    for (int c = 0; c < 4; c++)
#pragma unroll
        for (int r = 0; r < 4; r++) acc[c][r] = 0ull;

    float4 wa = *(const float4*)(W + 0*256 + col0);
    float4 wb = *(const float4*)(W + 1*256 + col0);

#pragma unroll 4
    for (int pk = 0; pk < 64; pk++) {
        int np = pk < 63 ? pk + 1 : 63;
        float4 wan = *(const float4*)(W + (2*np+0)*256 + col0);
        float4 wbn = *(const float4*)(W + (2*np+1)*256 + col0);

        unsigned long long w0 = pack2(wa.x, wb.x);
        unsigned long long w1 = pack2(wa.y, wb.y);
        unsigned long long w2 = pack2(wa.z, wb.z);
        unsigned long long w3 = pack2(wa.w, wb.w);
        unsigned long long a0 = A0[pk], a1 = A1[pk], a2 = A2[pk], a3 = A3[pk];

        ffma2(acc[0][0], a0, w0); ffma2(acc[0][1], a1, w0);
        ffma2(acc[0][2], a2, w0); ffma2(acc[0][3], a3, w0);
        ffma2(acc[1][0], a0, w1); ffma2(acc[1][1], a1, w1);
        ffma2(acc[1][2], a2, w1); ffma2(acc[1][3], a3, w1);
        ffma2(acc[2][0], a0, w2); ffma2(acc[2][1], a1, w2);
        ffma2(acc[2][2], a2, w2); ffma2(acc[2][3], a3, w2);
        ffma2(acc[3][0], a0, w3); ffma2(acc[3][1], a1, w3);
        ffma2(acc[3][2], a2, w3); ffma2(acc[3][3], a3, w3);

        wa = wan; wb = wbn;
    }

    float4 bb = *(const float4*)(bias + col0);
    float* dst; int cbase;
    if (outs && col0 >= 128) { dst = outs; cbase = col0 - 128; }
    else                     { dst = outc; cbase = col0; }
    int stride = outs ? DCH : 256;

#pragma unroll
    for (int r = 0; r < 4; r++) {
        float v0, v1, v2, v3, lo, hi;
        unpack2(acc[0][r], lo, hi); v0 = lo + hi + bb.x;
        unpack2(acc[1][r], lo, hi); v1 = lo + hi + bb.y;
        unpack2(acc[2][r], lo, hi); v2 = lo + hi + bb.z;
        unpack2(acc[3][r], lo, hi); v3 = lo + hi + bb.w;
        if (RELU) { v0=fmaxf(v0,0.f); v1=fmaxf(v1,0.f); v2=fmaxf(v2,0.f); v3=fmaxf(v3,0.f); }
        int row = r0 + rg*4 + r;
        *(float4*)&dst[(size_t)row*stride + cbase] = make_float4(v0,v1,v2,v3);
    }
}

__global__ __launch_bounds__(256) void gemm_split_kernel(
    const float* A, const float* sc, const float* sh,
    const float* W, const float* bias, float* fc, float* fs)
{
    __shared__ GemmSmem sm;
    gemm16_body<false>(&sm, A, sc, sh, W, bias, fc, fs, blockIdx.x*16);
}

__global__ __launch_bounds__(256) void gemm_dual_kernel(
    const float* A0, const float* sc0, const float* sh0, const float* W0, const float* b0,
    float* fc0, float* fs0,
    const float* A1, const float* sc1, const float* sh1, const float* W1, const float* b1,
    float* fc1, float* fs1)
{
    __shared__ GemmSmem sm;
    int bid = blockIdx.x;
    if (bid < 256) gemm16_body<false>(&sm, A0, sc0, sh0, W0, b0, fc0, fs0, bid*16);
    else           gemm16_body<false>(&sm, A1, sc1, sh1, W1, b1, fc1, fs1, (bid-256)*16);
}

// ---------------- final GEMM: K=384 (3 BN'd sources), relu ----------------------
__global__ __launch_bounds__(256) void gemm_final_kernel(
    const float* __restrict__ rl, const float* __restrict__ scl, const float* __restrict__ shl,
    const float* __restrict__ rm, const float* __restrict__ scm, const float* __restrict__ shm,
    const float* __restrict__ rg, const float* __restrict__ scg, const float* __restrict__ shg,
    const float* __restrict__ Wd, const float* __restrict__ bd, float* __restrict__ out)
{
    __shared__ unsigned long long in_s[16][193];
    int tid = threadIdx.x;
    int r0 = blockIdx.x * 16;

    const float* srcs[3] = {rl, rm, rg};
    const float* scs[3]  = {scl, scm, scg};
    const float* shs[3]  = {shl, shm, shg};
#pragma unroll
    for (int s = 0; s < 3; s++) {
        const float* A = srcs[s]; const float* sc = scs[s]; const float* sh = shs[s];
#pragma unroll
        for (int it = 0; it < 8; it++) {
            int idx = tid + it*256;
            int r = idx >> 7, k = idx & 127;
            float x = A[(size_t)(r0+r)*DCH + k];
            float val = fmaxf(fmaf(x, sc[k], sh[k]), 0.f);
            ((float*)&in_s[r][64*s + (k>>1)])[k&1] = val;
        }
    }
    __syncthreads();

    int col0 = (tid & 63) * 4;
    int rg_  = tid >> 6;
    const unsigned long long* A0 = in_s[rg_*4+0];
    const unsigned long long* A1 = in_s[rg_*4+1];
    const unsigned long long* A2 = in_s[rg_*4+2];
    const unsigned long long* A3 = in_s[rg_*4+3];

    unsigned long long acc[4][4];
#pragma unroll
    for (int c = 0; c < 4; c++)
#pragma unroll
        for (int r = 0; r < 4; r++) acc[c][r] = 0ull;

    float4 wa = *(const float4*)(Wd + 0*256 + col0);
    float4 wb = *(const float4*)(Wd + 1*256 + col0);

#pragma unroll 4
    for (int pk = 0; pk < 192; pk++) {
        int np = pk < 191 ? pk + 1 : 191;
        float4 wan = *(const float4*)(Wd + (2*np+0)*256 + col0);
        float4 wbn = *(const float4*)(Wd + (2*np+1)*256 + col0);

        unsigned long long w0 = pack2(wa.x, wb.x);
        unsigned long long w1 = pack2(wa.y, wb.y);
        unsigned long long w2 = pack2(wa.z, wb.z);
        unsigned long long w3 = pack2(wa.w, wb.w);
        unsigned long long a0 = A0[pk], a1 = A1[pk], a2 = A2[pk], a3 = A3[pk];

        ffma2(acc[0][0], a0, w0); ffma2(acc[0][1], a1, w0);
        ffma2(acc[0][2], a2, w0); ffma2(acc[0][3], a3, w0);
        ffma2(acc[1][0], a0, w1); ffma2(acc[1][1], a1, w1);
        ffma2(acc[1][2], a2, w1); ffma2(acc[1][3], a3, w1);
        ffma2(acc[2][0], a0, w2); ffma2(acc[2][1], a1, w2);
        ffma2(acc[2][2], a2, w2); ffma2(acc[2][3], a3, w2);
        ffma2(acc[3][0], a0, w3); ffma2(acc[3][1], a1, w3);
        ffma2(acc[3][2], a2, w3); ffma2(acc[3][3], a3, w3);

        wa = wan; wb = wbn;
    }

    float4 bb = *(const float4*)(bd + col0);
#pragma unroll
    for (int r = 0; r < 4; r++) {
        float v0, v1, v2, v3, lo, hi;
        unpack2(acc[0][r], lo, hi); v0 = fmaxf(lo + hi + bb.x, 0.f);
        unpack2(acc[1][r], lo, hi); v1 = fmaxf(lo + hi + bb.y, 0.f);
        unpack2(acc[2][r], lo, hi); v2 = fmaxf(lo + hi + bb.z, 0.f);
        unpack2(acc[3][r], lo, hi); v3 = fmaxf(lo + hi + bb.w, 0.f);
        int row = r0 + rg_*4 + r;
        *(float4*)&out[(size_t)row*256 + col0] = make_float4(v0,v1,v2,v3);
    }
}

// ================= layer conv ====================================================
__device__ __forceinline__ void conv_body(
    const float4* __restrict__ nd, const float* __restrict__ dirs,
    const float* __restrict__ fc, const float* __restrict__ fs,
    float* __restrict__ raw, int K, int p)
{
    int lane = threadIdx.x & 31;
    int rowbase = p & ~(NPTS-1);
    int col0 = lane*4;

    float d0[4], d1[4], d2[4];
#pragma unroll
    for (int c = 0; c < 4; c++) {
        int col = col0 + c;
        float a0 = dirs[col], a1 = dirs[128+col], a2 = dirs[256+col];
        float inv = 1.0f / fmaxf(sqrtf(a0*a0+a1*a1+a2*a2), 1e-12f);
        d0[c]=a0*inv; d1[c]=a1*inv; d2[c]=a2*inv;
    }

    float acc[4] = {-FLT_MAX, -FLT_MAX, -FLT_MAX, -FLT_MAX};
    const float4* ndp = nd + (size_t)p*KMAX;

#pragma unroll 8
    for (int kk = 0; kk < K; kk++) {
        float4 v = ndp[kk];
        int j = __float_as_int(v.w);
        float4 f = *(const float4*)(fs + (size_t)(rowbase + j)*DCH + col0);
        float t0 = fmaxf(v.x*d0[0] + v.y*d1[0] + v.z*d2[0], 0.0f);
        float t1 = fmaxf(v.x*d0[1] + v.y*d1[1] + v.z*d2[1], 0.0f);
        float t2 = fmaxf(v.x*d0[2] + v.y*d1[2] + v.z*d2[2], 0.0f);
        float t3 = fmaxf(v.x*d0[3] + v.y*d1[3] + v.z*d2[3], 0.0f);
        acc[0] = fmaxf(acc[0], t0*f.x);
        acc[1] = fmaxf(acc[1], t1*f.y);
        acc[2] = fmaxf(acc[2], t2*f.z);
        acc[3] = fmaxf(acc[3], t3*f.w);
    }

    float4 c4 = *(const float4*)(fc + (size_t)p*DCH + col0);
    *(float4*)&raw[(size_t)p*DCH + col0] =
        make_float4(c4.x + acc[0], c4.y + acc[1], c4.z + acc[2], c4.w + acc[3]);
}

__global__ __launch_bounds__(256) void conv_dual_kernel(
    const float4* nd,
    const float* dirs_m, const float* fc_m, const float* fs_m, float* raw_m,
    const float* dirs_g, const float* fc_g, const float* fs_g, float* raw_g)
{
    int bid = blockIdx.x, warp = threadIdx.x >> 5;
    if (bid < 512) conv_body(nd, dirs_m, fc_m, fs_m, raw_m, 20,  bid*8 + warp);
    else           conv_body(nd, dirs_g, fc_g, fs_g, raw_g, 100, (bid-512)*8 + warp);
}

__global__ __launch_bounds__(256) void conv_single_kernel(
    const float4* nd, const float* dirs, const float* fc, const float* fs, float* raw)
{
    conv_body(nd, dirs, fc, fs, raw, 100, blockIdx.x*8 + (threadIdx.x >> 5));
}

// ================= BN stats ======================================================
__device__ __forceinline__ void stats_body(const float* __restrict__ raw,
                                           const float* __restrict__ g,
                                           const float* __restrict__ be,
                                           float* __restrict__ scale,
                                           float* __restrict__ shift, int c4)
{
    int tid = threadIdx.x;
    float s0=0,s1=0,s2=0,s3=0,q0=0,q1=0,q2=0,q3=0;
    for (int r = tid; r < TOTAL; r += 256) {
        float4 v = *(const float4*)(raw + (size_t)r*DCH + c4);
        s0 += v.x; q0 += v.x*v.x;
        s1 += v.y; q1 += v.y*v.y;
        s2 += v.z; q2 += v.z*v.z;
        s3 += v.w; q3 += v.w*v.w;
    }
#pragma unroll
    for (int off = 16; off; off >>= 1) {
        s0 += __shfl_xor_sync(0xffffffffu, s0, off);
        s1 += __shfl_xor_sync(0xffffffffu, s1, off);
        s2 += __shfl_xor_sync(0xffffffffu, s2, off);
        s3 += __shfl_xor_sync(0xffffffffu, s3, off);
        q0 += __shfl_xor_sync(0xffffffffu, q0, off);
        q1 += __shfl_xor_sync(0xffffffffu, q1, off);
        q2 += __shfl_xor_sync(0xffffffffu, q2, off);
        q3 += __shfl_xor_sync(0xffffffffu, q3, off);
    }
    __shared__ float red[8][8];
    int warp = tid >> 5, lane = tid & 31;
    if (lane == 0) {
        red[warp][0]=s0; red[warp][1]=s1; red[warp][2]=s2; red[warp][3]=s3;
        red[warp][4]=q0; red[warp][5]=q1; red[warp][6]=q2; red[warp][7]=q3;
    }
    __syncthreads();
    if (tid < 8) {
        float t = 0.f;
#pragma unroll
        for (int w = 0; w < 8; w++) t += red[w][tid];
        red[0][tid] = t;
    }
    __syncthreads();
    if (tid < 4) {
        float mean = red[0][tid] * (1.0f/TOTAL);
        float var  = fmaxf(red[0][4+tid] * (1.0f/TOTAL) - mean*mean, 0.f);
        float sc   = g[c4+tid] * rsqrtf(var + 1e-5f);
        scale[c4+tid] = sc;
        shift[c4+tid] = be[c4+tid] - mean*sc;
    }
}

__global__ __launch_bounds__(256) void stats1_kernel(const float* raw, const float* g,
                                                     const float* be, float* scale, float* shift)
{
    stats_body(raw, g, be, scale, shift, blockIdx.x*4);
}

__global__ __launch_bounds__(256) void stats2_kernel(
    const float* r0, const float* g0, const float* b0, float* sc0, float* sh0,
    const float* r1, const float* g1, const float* b1, float* sc1, float* sh1)
{
    int stage = blockIdx.x >> 5;
    int c4 = (blockIdx.x & 31) * 4;
    if (stage == 0) stats_body(r0, g0, b0, sc0, sh0, c4);
    else            stats_body(r1, g1, b1, sc1, sh1, c4);
}

__global__ __launch_bounds__(256) void stats3_kernel(
    const float* r0, const float* g0, const float* b0, float* sc0, float* sh0,
    const float* r1, const float* g1, const float* b1, float* sc1, float* sh1,
    const float* r2, const float* g2, const float* b2, float* sc2, float* sh2)
{
    int stage = blockIdx.x >> 5;
    int c4 = (blockIdx.x & 31) * 4;
    if (stage == 0)      stats_body(r0, g0, b0, sc0, sh0, c4);
    else if (stage == 1) stats_body(r1, g1, b1, sc1, sh1, c4);
    else                 stats_body(r2, g2, b2, sc2, sh2, c4);
}

// ================= launcher ======================================================
extern "C" void kernel_launch(void* const* d_in, const int* in_sizes, int n_in,
                              void* d_out, int out_size)
{
    const float* verts   = (const float*)d_in[0];
    const float* dirs_l  = (const float*)d_in[1];
    const float* dirs_m0 = (const float*)d_in[2];
    const float* W_m1    = (const float*)d_in[3];
    const float* b_m1    = (const float*)d_in[4];
    const float* dirs_m1 = (const float*)d_in[5];
    const float* dirs_g0 = (const float*)d_in[6];
    const float* W_g1    = (const float*)d_in[7];
    const float* b_g1    = (const float*)d_in[8];
    const float* dirs_g1 = (const float*)d_in[9];
    const float* W_g2    = (const float*)d_in[10];
    const float* b_g2    = (const float*)d_in[11];
    const float* dirs_g2 = (const float*)d_in[12];
    const float* g_l   = (const float*)d_in[13];
    const float* be_l  = (const float*)d_in[14];
    const float* g_m0  = (const float*)d_in[15];
    const float* be_m0 = (const float*)d_in[16];
    const float* g_m1  = (const float*)d_in[17];
    const float* be_m1 = (const float*)d_in[18];
    const float* g_g0  = (const float*)d_in[19];
    const float* be_g0 = (const float*)d_in[20];
    const float* g_g1  = (const float*)d_in[21];
    const float* be_g1 = (const float*)d_in[22];
    const float* g_g2  = (const float*)d_in[23];
    const float* be_g2 = (const float*)d_in[24];
    const float* W_down = (const float*)d_in[25];
    const float* b_down = (const float*)d_in[26];
    float* out = (float*)d_out;

    float4* nd;    cudaGetSymbolAddress((void**)&nd,    g_nd);
    float*  raw;   cudaGetSymbolAddress((void**)&raw,   g_raw);
    float*  fc_m;  cudaGetSymbolAddress((void**)&fc_m,  g_fc_m);
    float*  fs_m;  cudaGetSymbolAddress((void**)&fs_m,  g_fs_m);
    float*  fc_g;  cudaGetSymbolAddress((void**)&fc_g,  g_fc_g);
    float*  fs_g;  cudaGetSymbolAddress((void**)&fs_g,  g_fs_g);
    float*  scale; cudaGetSymbolAddress((void**)&scale, g_scale);
    float*  shift; cudaGetSymbolAddress((void**)&shift, g_shift);

#define RAW(s) (raw + (size_t)(s)*TOTAL*DCH)
#define SC(s)  (scale + (s)*DCH)
#define SH(s)  (shift + (s)*DCH)

    // 1) KNN (exact rank select, block per point) + all three surface convs
    knn_surf_kernel<<<TOTAL, 128>>>(verts, nd, RAW(0), RAW(1), RAW(3),
                                    dirs_l, dirs_m0, dirs_g0);
    // 2) BN stats for l, m0, g0
    stats3_kernel<<<96, 256>>>(RAW(0), g_l,  be_l,  SC(0), SH(0),
                               RAW(1), g_m0, be_m0, SC(1), SH(1),
                               RAW(3), g_g0, be_g0, SC(3), SH(3));
    // 3) fm@W for medium and global-1 in one grid
    gemm_dual_kernel<<<512, 256>>>(RAW(1), SC(1), SH(1), W_m1, b_m1, fc_m, fs_m,
                                   RAW(3), SC(3), SH(3), W_g1, b_g1, fc_g, fs_g);
    // 4) layer convs m (K=20) and g1 (K=100) in one grid
    conv_dual_kernel<<<1024, 256>>>(nd, dirs_m1, fc_m, fs_m, RAW(2),
                                        dirs_g1, fc_g, fs_g, RAW(4));
    // 5) BN stats m1 + g1
    stats2_kernel<<<64, 256>>>(RAW(2), g_m1, be_m1, SC(2), SH(2),
                               RAW(4), g_g1, be_g1, SC(4), SH(4));
    // 6) global-2 fm@W
    gemm_split_kernel<<<256, 256>>>(RAW(4), SC(4), SH(4), W_g2, b_g2, fc_g, fs_g);
    // 7) global-2 layer conv (K=100)
    conv_single_kernel<<<512, 256>>>(nd, dirs_g2, fc_g, fs_g, RAW(5));
    // 8) BN stats g2
    stats1_kernel<<<32, 256>>>(RAW(5), g_g2, be_g2, SC(5), SH(5));
    // 9) concat + down projection + relu
    gemm_final_kernel<<<256, 256>>>(RAW(0), SC(0), SH(0),
                                    RAW(2), SC(2), SH(2),
                                    RAW(5), SC(5), SH(5),
                                    W_down, b_down, out);
#undef RAW
#undef SC
#undef SH
}

// round 7
// speedup vs baseline: 2.2720x; 1.0112x over previous
#include <cuda_runtime.h>
#include <math.h>
#include <float.h>

#define NPTS   1024
#define BATCH  4
#define TOTAL  (BATCH*NPTS)      // 4096
#define DCH    128
#define KMAX   100

// ---------------- scratch (static device globals; no allocation) ----------------
__device__ float4 g_nd[TOTAL*KMAX];          // normalized edge dirs + idx in .w (sorted)
__device__ float  g_raw[6][TOTAL*DCH];       // raw (pre-BN) features per stage
__device__ float  g_fc_m[TOTAL*DCH];
__device__ float  g_fs_m[TOTAL*DCH];
__device__ float  g_fc_g[TOTAL*DCH];
__device__ float  g_fs_g[TOTAL*DCH];
__device__ float  g_scale[6*DCH];
__device__ float  g_shift[6*DCH];

// ---------------- f32x2 helpers -------------------------------------------------
__device__ __forceinline__ unsigned long long pack2(float a, float b) {
    unsigned long long r;
    asm("mov.b64 %0, {%1, %2};" : "=l"(r) : "f"(a), "f"(b));
    return r;
}
__device__ __forceinline__ void unpack2(unsigned long long v, float &a, float &b) {
    asm("mov.b64 {%0, %1}, %2;" : "=f"(a), "=f"(b) : "l"(v));
}
__device__ __forceinline__ void ffma2(unsigned long long &d, unsigned long long a, unsigned long long b) {
    asm("fma.rn.f32x2 %0, %1, %2, %3;" : "=l"(d) : "l"(a), "l"(b), "l"(d));
}

// padded word index for conflict-free 2048-bucket (1024-word) histogram
#define PW(w) ((w) + ((w) >> 5))
#define HWORDS 1056                            // 1024 + 32 pad

// ================= KNN (2 points/block, exact rank select) + surface convs ======
__global__ __launch_bounds__(256) void knn_surf_kernel(
    const float* __restrict__ verts, float4* __restrict__ nd,
    float* __restrict__ raw_l, float* __restrict__ raw_m, float* __restrict__ raw_g,
    const float* __restrict__ dl, const float* __restrict__ dm, const float* __restrict__ dg)
{
    __shared__ float vx[NPTS], vy[NPTS], vz[NPTS];
    __shared__ unsigned int hist[2*HWORDS];           // u16-packed counts
    __shared__ unsigned long long list_s[2][NPTS];
    __shared__ unsigned long long sel_s[2][104];
    __shared__ float ndx_s[2][100], ndy_s[2][100], ndz_s[2][100];
    __shared__ float gacc_s[2][4][128];
    __shared__ unsigned int chunk_s[2][128];
    __shared__ unsigned int wtot[2][4];
    __shared__ unsigned int cnt_s[2], selcnt_s[2], B_s[2], q_s[2];
    __shared__ unsigned long long T_s[2];

    int tid = threadIdx.x;
    int pt  = tid >> 7;                 // which of the 2 points
    int st  = tid & 127;                // sub-thread within point
    int p0  = blockIdx.x * 2;
    int b   = p0 >> 10;                 // p0 even -> both points same batch
    int p   = p0 + pt;
    int i   = p & (NPTS-1);
    const float* vb = verts + b*NPTS*3;

    for (int t = tid; t < NPTS; t += 256) {
        vx[t] = vb[3*t+0]; vy[t] = vb[3*t+1]; vz[t] = vb[3*t+2];
    }
    for (int t = tid; t < 2*HWORDS; t += 256) hist[t] = 0;
    if (tid < 2) { cnt_s[tid] = 0; selcnt_s[tid] = 0; }
    __syncthreads();

    float xi = vx[i], yi = vy[i], zi = vz[i];
    float sqi = xi*xi + yi*yi + zi*zi;
    int wb = pt * HWORDS;

    unsigned long long k64[8];
#pragma unroll
    for (int s = 0; s < 8; s++) {
        int j = st + s*128;
        float xj = vx[j], yj = vy[j], zj = vz[j];
        float sqj = xj*xj + yj*yj + zj*zj;
        float dot = xi*xj + yi*yj + zi*zj;
        float d   = sqi + sqj - 2.0f*dot;             // same formula as reference
        unsigned int bits = __float_as_uint(d);
        unsigned int key  = (bits & 0x80000000u) ? ~bits : (bits | 0x80000000u);
        k64[s] = ((unsigned long long)key << 10) | (unsigned)j;
        unsigned int bu = key >> 21;                  // 11-bit bucket
        atomicAdd(&hist[wb + PW(bu>>1)], (bu & 1u) ? 65536u : 1u);
    }
    __syncthreads();

    // ---- scan of 2048 bucket counts per point (16 buckets = 8 words / thread) ----
    {
        unsigned int run = 0;
#pragma unroll
        for (int t = 0; t < 8; t++) {
            unsigned int v = hist[wb + PW(st*8 + t)];
            run += (v & 0xffffu) + (v >> 16);
        }
        chunk_s[pt][st] = run;
    }
    __syncthreads();

    int lane = tid & 31, warp = tid >> 5;    // warps 0-3 -> pt0, 4-7 -> pt1
    int sw = st >> 5;
    unsigned int xv = chunk_s[pt][st];
    unsigned int inc = xv;
#pragma unroll
    for (int off = 1; off < 32; off <<= 1) {
        unsigned int y = __shfl_up_sync(0xffffffffu, inc, off);
        if (lane >= off) inc += y;
    }
    if (lane == 31) wtot[pt][sw] = inc;
    __syncthreads();
    unsigned int wbase = 0;
    for (int w = 0; w < sw; w++) wbase += wtot[pt][w];
    unsigned int chunk_base = wbase + inc - xv;

    // ---- locate bucket holding global rank 100 ----
    {
        unsigned int pr = chunk_base;
#pragma unroll
        for (int t = 0; t < 16; t++) {
            int bu = st*16 + t;
            unsigned int v = hist[wb + PW(bu>>1)];
            unsigned int c = (bu & 1) ? (v >> 16) : (v & 0xffffu);
            if (pr <= 100u && 100u < pr + c) { B_s[pt] = (unsigned)bu; q_s[pt] = 100u - pr; }
            pr += c;
        }
    }
    __syncthreads();

    unsigned int B = B_s[pt], q = q_s[pt];
    // ---- collect that bucket's elements ----
#pragma unroll
    for (int s = 0; s < 8; s++) {
        unsigned int bu = (unsigned int)(k64[s] >> 31);       // key>>21
        if (bu == B) { unsigned int idx = atomicAdd(&cnt_s[pt], 1u); list_s[pt][idx] = k64[s]; }
    }
    __syncthreads();
    unsigned int cnt = cnt_s[pt];
    for (unsigned int ii = st; ii < cnt; ii += 128) {
        unsigned long long me = list_s[pt][ii];
        unsigned int r = 0;
        for (unsigned int j2 = 0; j2 < cnt; j2++) r += (list_s[pt][j2] < me) ? 1u : 0u;
        if (r == q) T_s[pt] = me;
    }
    __syncthreads();
    unsigned long long T = T_s[pt];

    // ---- compact the 101 smallest (keys unique -> exactly 101) ----
#pragma unroll
    for (int s = 0; s < 8; s++) {
        if (k64[s] <= T) { unsigned int idx = atomicAdd(&selcnt_s[pt], 1u); sel_s[pt][idx] = k64[s]; }
    }
    __syncthreads();

    // ---- rank the 101, emit sorted nd (rank 0 = self dropped) ----
    if (st < 101) {
        unsigned long long me = sel_s[pt][st];
        unsigned int r = 0;
#pragma unroll 4
        for (int j2 = 0; j2 < 101; j2++) r += (sel_s[pt][j2] < me) ? 1u : 0u;
        if (r > 0) {
            int slot = (int)r - 1;
            int j = (int)(me & 1023u);
            float dx = vx[j]-xi, dy = vy[j]-yi, dz = vz[j]-zi;
            float inv = 1.0f / fmaxf(sqrtf(dx*dx + dy*dy + dz*dz), 1e-12f);
            float nx = dx*inv, ny = dy*inv, nz = dz*inv;
            ndx_s[pt][slot] = nx; ndy_s[pt][slot] = ny; ndz_s[pt][slot] = nz;
            nd[(size_t)p*KMAX + slot] = make_float4(nx, ny, nz, __int_as_float(j));
        }
    }
    __syncthreads();

    // ---- surface convs: sub-warp sw handles slots [sw*25, sw*25+25) ----
    int col0 = lane*4;
    float q0[4], q1[4], q2[4];
#pragma unroll
    for (int c = 0; c < 4; c++) {
        int col = col0 + c;
        float a0 = dg[col], a1 = dg[128+col], a2 = dg[256+col];
        float inv = 1.0f / fmaxf(sqrtf(a0*a0+a1*a1+a2*a2), 1e-12f);
        q0[c]=a0*inv; q1[c]=a1*inv; q2[c]=a2*inv;
    }
    float accg[4] = {0,0,0,0};

    if (sw == 0) {
        float l0[4], l1[4], l2[4], m0[4], m1[4], m2[4];
#pragma unroll
        for (int c = 0; c < 4; c++) {
            int col = col0 + c;
            float a0, a1, a2, inv;
            a0 = dl[col]; a1 = dl[128+col]; a2 = dl[256+col];
            inv = 1.0f / fmaxf(sqrtf(a0*a0+a1*a1+a2*a2), 1e-12f);
            l0[c]=a0*inv; l1[c]=a1*inv; l2[c]=a2*inv;
            a0 = dm[col]; a1 = dm[128+col]; a2 = dm[256+col];
            inv = 1.0f / fmaxf(sqrtf(a0*a0+a1*a1+a2*a2), 1e-12f);
            m0[c]=a0*inv; m1[c]=a1*inv; m2[c]=a2*inv;
        }
        float accl[4] = {0,0,0,0}, accm[4] = {0,0,0,0};
#pragma unroll 1
        for (int s = 0; s < 25; s++) {
            float nx = ndx_s[pt][s], ny = ndy_s[pt][s], nz = ndz_s[pt][s];
#pragma unroll
            for (int c = 0; c < 4; c++)
                accg[c] = fmaxf(accg[c], nx*q0[c] + ny*q1[c] + nz*q2[c]);
            if (s < 20) {
#pragma unroll
                for (int c = 0; c < 4; c++)
                    accm[c] = fmaxf(accm[c], nx*m0[c] + ny*m1[c] + nz*m2[c]);
            }
            if (s < 5) {
#pragma unroll
                for (int c = 0; c < 4; c++)
                    accl[c] = fmaxf(accl[c], nx*l0[c] + ny*l1[c] + nz*l2[c]);
            }
        }
        *(float4*)&raw_l[(size_t)p*DCH + col0] = make_float4(accl[0],accl[1],accl[2],accl[3]);
        *(float4*)&raw_m[(size_t)p*DCH + col0] = make_float4(accm[0],accm[1],accm[2],accm[3]);
    } else {
        int sbeg = sw*25;
#pragma unroll 1
        for (int s = sbeg; s < sbeg + 25; s++) {
            float nx = ndx_s[pt][s], ny = ndy_s[pt][s], nz = ndz_s[pt][s];
#pragma unroll
            for (int c = 0; c < 4; c++)
                accg[c] = fmaxf(accg[c], nx*q0[c] + ny*q1[c] + nz*q2[c]);
        }
    }
    *(float4*)&gacc_s[pt][sw][col0] = make_float4(accg[0],accg[1],accg[2],accg[3]);
    __syncthreads();
    float gm = fmaxf(fmaxf(gacc_s[pt][0][st], gacc_s[pt][1][st]),
                     fmaxf(gacc_s[pt][2][st], gacc_s[pt][3][st]));
    raw_g[(size_t)p*DCH + st] = gm;
}

// ================= GEMM core: 16 rows x 256 cols, k-pair f32x2 ===================
struct GemmSmem { unsigned long long in_s[16][65]; };

template<bool RELU>
__device__ __forceinline__ void gemm16_body(
    GemmSmem* sm,
    const float* __restrict__ A, const float* __restrict__ sc, const float* __restrict__ sh,
    const float* __restrict__ W, const float* __restrict__ bias,
    float* __restrict__ outc, float* __restrict__ outs, int r0)
{
    int tid = threadIdx.x;
#pragma unroll
    for (int it = 0; it < 8; it++) {
        int idx = tid + it*256;
        int r = idx >> 7, k = idx & 127;
        float x = A[(size_t)(r0+r)*DCH + k];
        float val = fmaxf(fmaf(x, sc[k], sh[k]), 0.f);
        ((float*)&sm->in_s[r][k>>1])[k&1] = val;
    }
    __syncthreads();

    int col0 = (tid & 63) * 4;
    int rg   = tid >> 6;
    const unsigned long long* A0 = sm->in_s[rg*4+0];
    const unsigned long long* A1 = sm->in_s[rg*4+1];
    const unsigned long long* A2 = sm->in_s[rg*4+2];
    const unsigned long long* A3 = sm->in_s[rg*4+3];

    unsigned long long acc[4][4];
#pragma unroll
    for (int c = 0; c < 4; c++)
#pragma unroll
        for (int r = 0; r < 4; r++) acc[c][r] = 0ull;

    float4 wa = *(const float4*)(W + 0*256 + col0);
    float4 wb = *(const float4*)(W + 1*256 + col0);

#pragma unroll 4
    for (int pk = 0; pk < 64; pk++) {
        int np = pk < 63 ? pk + 1 : 63;
        float4 wan = *(const float4*)(W + (2*np+0)*256 + col0);
        float4 wbn = *(const float4*)(W + (2*np+1)*256 + col0);

        unsigned long long w0 = pack2(wa.x, wb.x);
        unsigned long long w1 = pack2(wa.y, wb.y);
        unsigned long long w2 = pack2(wa.z, wb.z);
        unsigned long long w3 = pack2(wa.w, wb.w);
        unsigned long long a0 = A0[pk], a1 = A1[pk], a2 = A2[pk], a3 = A3[pk];

        ffma2(acc[0][0], a0, w0); ffma2(acc[0][1], a1, w0);
        ffma2(acc[0][2], a2, w0); ffma2(acc[0][3], a3, w0);
        ffma2(acc[1][0], a0, w1); ffma2(acc[1][1], a1, w1);
        ffma2(acc[1][2], a2, w1); ffma2(acc[1][3], a3, w1);
        ffma2(acc[2][0], a0, w2); ffma2(acc[2][1], a1, w2);
        ffma2(acc[2][2], a2, w2); ffma2(acc[2][3], a3, w2);
        ffma2(acc[3][0], a0, w3); ffma2(acc[3][1], a1, w3);
        ffma2(acc[3][2], a2, w3); ffma2(acc[3][3], a3, w3);

        wa = wan; wb = wbn;
    }

    float4 bb = *(const float4*)(bias + col0);
    float* dst; int cbase;
    if (outs && col0 >= 128) { dst = outs; cbase = col0 - 128; }
    else                     { dst = outc; cbase = col0; }
    int stride = outs ? DCH : 256;

#pragma unroll
    for (int r = 0; r < 4; r++) {
        float v0, v1, v2, v3, lo, hi;
        unpack2(acc[0][r], lo, hi); v0 = lo + hi + bb.x;
        unpack2(acc[1][r], lo, hi); v1 = lo + hi + bb.y;
        unpack2(acc[2][r], lo, hi); v2 = lo + hi + bb.z;
        unpack2(acc[3][r], lo, hi); v3 = lo + hi + bb.w;
        if (RELU) { v0=fmaxf(v0,0.f); v1=fmaxf(v1,0.f); v2=fmaxf(v2,0.f); v3=fmaxf(v3,0.f); }
        int row = r0 + rg*4 + r;
        *(float4*)&dst[(size_t)row*stride + cbase] = make_float4(v0,v1,v2,v3);
    }
}

__global__ __launch_bounds__(256) void gemm_split_kernel(
    const float* A, const float* sc, const float* sh,
    const float* W, const float* bias, float* fc, float* fs)
{
    __shared__ GemmSmem sm;
    gemm16_body<false>(&sm, A, sc, sh, W, bias, fc, fs, blockIdx.x*16);
}

__global__ __launch_bounds__(256) void gemm_dual_kernel(
    const float* A0, const float* sc0, const float* sh0, const float* W0, const float* b0,
    float* fc0, float* fs0,
    const float* A1, const float* sc1, const float* sh1, const float* W1, const float* b1,
    float* fc1, float* fs1)
{
    __shared__ GemmSmem sm;
    int bid = blockIdx.x;
    if (bid < 256) gemm16_body<false>(&sm, A0, sc0, sh0, W0, b0, fc0, fs0, bid*16);
    else           gemm16_body<false>(&sm, A1, sc1, sh1, W1, b1, fc1, fs1, (bid-256)*16);
}

// ---------------- final GEMM: K=384 (3 BN'd sources), relu ----------------------
__global__ __launch_bounds__(256) void gemm_final_kernel(
    const float* __restrict__ rl, const float* __restrict__ scl, const float* __restrict__ shl,
    const float* __restrict__ rm, const float* __restrict__ scm, const float* __restrict__ shm,
    const float* __restrict__ rg, const float* __restrict__ scg, const float* __restrict__ shg,
    const float* __restrict__ Wd, const float* __restrict__ bd, float* __restrict__ out)
{
    __shared__ unsigned long long in_s[16][193];
    int tid = threadIdx.x;
    int r0 = blockIdx.x * 16;

    const float* srcs[3] = {rl, rm, rg};
    const float* scs[3]  = {scl, scm, scg};
    const float* shs[3]  = {shl, shm, shg};
#pragma unroll
    for (int s = 0; s < 3; s++) {
        const float* A = srcs[s]; const float* sc = scs[s]; const float* sh = shs[s];
#pragma unroll
        for (int it = 0; it < 8; it++) {
            int idx = tid + it*256;
            int r = idx >> 7, k = idx & 127;
            float x = A[(size_t)(r0+r)*DCH + k];
            float val = fmaxf(fmaf(x, sc[k], sh[k]), 0.f);
            ((float*)&in_s[r][64*s + (k>>1)])[k&1] = val;
        }
    }
    __syncthreads();

    int col0 = (tid & 63) * 4;
    int rg_  = tid >> 6;
    const unsigned long long* A0 = in_s[rg_*4+0];
    const unsigned long long* A1 = in_s[rg_*4+1];
    const unsigned long long* A2 = in_s[rg_*4+2];
    const unsigned long long* A3 = in_s[rg_*4+3];

    unsigned long long acc[4][4];
#pragma unroll
    for (int c = 0; c < 4; c++)
#pragma unroll
        for (int r = 0; r < 4; r++) acc[c][r] = 0ull;

    float4 wa = *(const float4*)(Wd + 0*256 + col0);
    float4 wb = *(const float4*)(Wd + 1*256 + col0);

#pragma unroll 4
    for (int pk = 0; pk < 192; pk++) {
        int np = pk < 191 ? pk + 1 : 191;
        float4 wan = *(const float4*)(Wd + (2*np+0)*256 + col0);
        float4 wbn = *(const float4*)(Wd + (2*np+1)*256 + col0);

        unsigned long long w0 = pack2(wa.x, wb.x);
        unsigned long long w1 = pack2(wa.y, wb.y);
        unsigned long long w2 = pack2(wa.z, wb.z);
        unsigned long long w3 = pack2(wa.w, wb.w);
        unsigned long long a0 = A0[pk], a1 = A1[pk], a2 = A2[pk], a3 = A3[pk];

        ffma2(acc[0][0], a0, w0); ffma2(acc[0][1], a1, w0);
        ffma2(acc[0][2], a2, w0); ffma2(acc[0][3], a3, w0);
        ffma2(acc[1][0], a0, w1); ffma2(acc[1][1], a1, w1);
        ffma2(acc[1][2], a2, w1); ffma2(acc[1][3], a3, w1);
        ffma2(acc[2][0], a0, w2); ffma2(acc[2][1], a1, w2);
        ffma2(acc[2][2], a2, w2); ffma2(acc[2][3], a3, w2);
        ffma2(acc[3][0], a0, w3); ffma2(acc[3][1], a1, w3);
        ffma2(acc[3][2], a2, w3); ffma2(acc[3][3], a3, w3);

        wa = wan; wb = wbn;
    }

    float4 bb = *(const float4*)(bd + col0);
#pragma unroll
    for (int r = 0; r < 4; r++) {
        float v0, v1, v2, v3, lo, hi;
        unpack2(acc[0][r], lo, hi); v0 = fmaxf(lo + hi + bb.x, 0.f);
        unpack2(acc[1][r], lo, hi); v1 = fmaxf(lo + hi + bb.y, 0.f);
        unpack2(acc[2][r], lo, hi); v2 = fmaxf(lo + hi + bb.z, 0.f);
        unpack2(acc[3][r], lo, hi); v3 = fmaxf(lo + hi + bb.w, 0.f);
        int row = r0 + rg_*4 + r;
        *(float4*)&out[(size_t)row*256 + col0] = make_float4(v0,v1,v2,v3);
    }
}

// ================= layer conv: warp-pair per point (K split in halves) ===========
// block = 256 thr = 8 warps = 4 points; warp (2u, 2u+1) -> point u's K-halves.
__device__ __forceinline__ void conv_pair_body(
    const float4* __restrict__ nd, const float* __restrict__ dirs,
    const float* __restrict__ fc, const float* __restrict__ fs,
    float* __restrict__ raw, int K, int pbase, float* sacc)
{
    int tid = threadIdx.x;
    int lane = tid & 31, warp = tid >> 5;
    int pp = warp >> 1;                 // point within block (0..3)
    int khalf = warp & 1;
    int p = pbase + pp;
    int rowbase = p & ~(NPTS-1);
    int col0 = lane*4;

    float d0[4], d1[4], d2[4];
#pragma unroll
    for (int c = 0; c < 4; c++) {
        int col = col0 + c;
        float a0 = dirs[col], a1 = dirs[128+col], a2 = dirs[256+col];
        float inv = 1.0f / fmaxf(sqrtf(a0*a0+a1*a1+a2*a2), 1e-12f);
        d0[c]=a0*inv; d1[c]=a1*inv; d2[c]=a2*inv;
    }

    float acc[4] = {-FLT_MAX, -FLT_MAX, -FLT_MAX, -FLT_MAX};
    const float4* ndp = nd + (size_t)p*KMAX;
    int k0 = khalf * (K >> 1);
    int k1 = k0 + (K >> 1);

#pragma unroll 5
    for (int kk = k0; kk < k1; kk++) {
        float4 v = ndp[kk];
        int j = __float_as_int(v.w);
        float4 f = *(const float4*)(fs + (size_t)(rowbase + j)*DCH + col0);
        float t0 = fmaxf(v.x*d0[0] + v.y*d1[0] + v.z*d2[0], 0.0f);
        float t1 = fmaxf(v.x*d0[1] + v.y*d1[1] + v.z*d2[1], 0.0f);
        float t2 = fmaxf(v.x*d0[2] + v.y*d1[2] + v.z*d2[2], 0.0f);
        float t3 = fmaxf(v.x*d0[3] + v.y*d1[3] + v.z*d2[3], 0.0f);
        acc[0] = fmaxf(acc[0], t0*f.x);
        acc[1] = fmaxf(acc[1], t1*f.y);
        acc[2] = fmaxf(acc[2], t2*f.z);
        acc[3] = fmaxf(acc[3], t3*f.w);
    }

    *(float4*)&sacc[warp*128 + col0] = make_float4(acc[0], acc[1], acc[2], acc[3]);
    __syncthreads();

    // combine halves: 4 points x 128 ch = 512 items / 256 thr
#pragma unroll
    for (int it = 0; it < 2; it++) {
        int idx = tid + it*256;
        int qq = idx >> 7;              // point within block
        int c  = idx & 127;
        float vmx = fmaxf(sacc[(2*qq)*128 + c], sacc[(2*qq+1)*128 + c]);
        int pq = pbase + qq;
        raw[(size_t)pq*DCH + c] = fc[(size_t)pq*DCH + c] + vmx;
    }
}

__global__ __launch_bounds__(256) void conv_dual_kernel(
    const float4* nd,
    const float* dirs_m, const float* fc_m, const float* fs_m, float* raw_m,
    const float* dirs_g, const float* fc_g, const float* fs_g, float* raw_g)
{
    __shared__ float sacc[8*128];
    int bid = blockIdx.x;
    if (bid < 1024) conv_pair_body(nd, dirs_m, fc_m, fs_m, raw_m, 20,  bid*4, sacc);
    else            conv_pair_body(nd, dirs_g, fc_g, fs_g, raw_g, 100, (bid-1024)*4, sacc);
}

__global__ __launch_bounds__(256) void conv_single_kernel(
    const float4* nd, const float* dirs, const float* fc, const float* fs, float* raw)
{
    __shared__ float sacc[8*128];
    conv_pair_body(nd, dirs, fc, fs, raw, 100, blockIdx.x*4, sacc);
}

// ================= BN stats ======================================================
__device__ __forceinline__ void stats_body(const float* __restrict__ raw,
                                           const float* __restrict__ g,
                                           const float* __restrict__ be,
                                           float* __restrict__ scale,
                                           float* __restrict__ shift, int c4)
{
    int tid = threadIdx.x;
    float s0=0,s1=0,s2=0,s3=0,q0=0,q1=0,q2=0,q3=0;
    for (int r = tid; r < TOTAL; r += 256) {
        float4 v = *(const float4*)(raw + (size_t)r*DCH + c4);
        s0 += v.x; q0 += v.x*v.x;
        s1 += v.y; q1 += v.y*v.y;
        s2 += v.z; q2 += v.z*v.z;
        s3 += v.w; q3 += v.w*v.w;
    }
#pragma unroll
    for (int off = 16; off; off >>= 1) {
        s0 += __shfl_xor_sync(0xffffffffu, s0, off);
        s1 += __shfl_xor_sync(0xffffffffu, s1, off);
        s2 += __shfl_xor_sync(0xffffffffu, s2, off);
        s3 += __shfl_xor_sync(0xffffffffu, s3, off);
        q0 += __shfl_xor_sync(0xffffffffu, q0, off);
        q1 += __shfl_xor_sync(0xffffffffu, q1, off);
        q2 += __shfl_xor_sync(0xffffffffu, q2, off);
        q3 += __shfl_xor_sync(0xffffffffu, q3, off);
    }
    __shared__ float red[8][8];
    int warp = tid >> 5, lane = tid & 31;
    if (lane == 0) {
        red[warp][0]=s0; red[warp][1]=s1; red[warp][2]=s2; red[warp][3]=s3;
        red[warp][4]=q0; red[warp][5]=q1; red[warp][6]=q2; red[warp][7]=q3;
    }
    __syncthreads();
    if (tid < 8) {
        float t = 0.f;
#pragma unroll
        for (int w = 0; w < 8; w++) t += red[w][tid];
        red[0][tid] = t;
    }
    __syncthreads();
    if (tid < 4) {
        float mean = red[0][tid] * (1.0f/TOTAL);
        float var  = fmaxf(red[0][4+tid] * (1.0f/TOTAL) - mean*mean, 0.f);
        float sc   = g[c4+tid] * rsqrtf(var + 1e-5f);
        scale[c4+tid] = sc;
        shift[c4+tid] = be[c4+tid] - mean*sc;
    }
}

__global__ __launch_bounds__(256) void stats1_kernel(const float* raw, const float* g,
                                                     const float* be, float* scale, float* shift)
{
    stats_body(raw, g, be, scale, shift, blockIdx.x*4);
}

__global__ __launch_bounds__(256) void stats2_kernel(
    const float* r0, const float* g0, const float* b0, float* sc0, float* sh0,
    const float* r1, const float* g1, const float* b1, float* sc1, float* sh1)
{
    int stage = blockIdx.x >> 5;
    int c4 = (blockIdx.x & 31) * 4;
    if (stage == 0) stats_body(r0, g0, b0, sc0, sh0, c4);
    else            stats_body(r1, g1, b1, sc1, sh1, c4);
}

__global__ __launch_bounds__(256) void stats3_kernel(
    const float* r0, const float* g0, const float* b0, float* sc0, float* sh0,
    const float* r1, const float* g1, const float* b1, float* sc1, float* sh1,
    const float* r2, const float* g2, const float* b2, float* sc2, float* sh2)
{
    int stage = blockIdx.x >> 5;
    int c4 = (blockIdx.x & 31) * 4;
    if (stage == 0)      stats_body(r0, g0, b0, sc0, sh0, c4);
    else if (stage == 1) stats_body(r1, g1, b1, sc1, sh1, c4);
    else                 stats_body(r2, g2, b2, sc2, sh2, c4);
}

// ================= launcher ======================================================
extern "C" void kernel_launch(void* const* d_in, const int* in_sizes, int n_in,
                              void* d_out, int out_size)
{
    const float* verts   = (const float*)d_in[0];
    const float* dirs_l  = (const float*)d_in[1];
    const float* dirs_m0 = (const float*)d_in[2];
    const float* W_m1    = (const float*)d_in[3];
    const float* b_m1    = (const float*)d_in[4];
    const float* dirs_m1 = (const float*)d_in[5];
    const float* dirs_g0 = (const float*)d_in[6];
    const float* W_g1    = (const float*)d_in[7];
    const float* b_g1    = (const float*)d_in[8];
    const float* dirs_g1 = (const float*)d_in[9];
    const float* W_g2    = (const float*)d_in[10];
    const float* b_g2    = (const float*)d_in[11];
    const float* dirs_g2 = (const float*)d_in[12];
    const float* g_l   = (const float*)d_in[13];
    const float* be_l  = (const float*)d_in[14];
    const float* g_m0  = (const float*)d_in[15];
    const float* be_m0 = (const float*)d_in[16];
    const float* g_m1  = (const float*)d_in[17];
    const float* be_m1 = (const float*)d_in[18];
    const float* g_g0  = (const float*)d_in[19];
    const float* be_g0 = (const float*)d_in[20];
    const float* g_g1  = (const float*)d_in[21];
    const float* be_g1 = (const float*)d_in[22];
    const float* g_g2  = (const float*)d_in[23];
    const float* be_g2 = (const float*)d_in[24];
    const float* W_down = (const float*)d_in[25];
    const float* b_down = (const float*)d_in[26];
    float* out = (float*)d_out;

    float4* nd;    cudaGetSymbolAddress((void**)&nd,    g_nd);
    float*  raw;   cudaGetSymbolAddress((void**)&raw,   g_raw);
    float*  fc_m;  cudaGetSymbolAddress((void**)&fc_m,  g_fc_m);
    float*  fs_m;  cudaGetSymbolAddress((void**)&fs_m,  g_fs_m);
    float*  fc_g;  cudaGetSymbolAddress((void**)&fc_g,  g_fc_g);
    float*  fs_g;  cudaGetSymbolAddress((void**)&fs_g,  g_fs_g);
    float*  scale; cudaGetSymbolAddress((void**)&scale, g_scale);
    float*  shift; cudaGetSymbolAddress((void**)&shift, g_shift);

#define RAW(s) (raw + (size_t)(s)*TOTAL*DCH)
#define SC(s)  (scale + (s)*DCH)
#define SH(s)  (shift + (s)*DCH)

    // 1) KNN (2 points/block) + all three surface convs
    knn_surf_kernel<<<TOTAL/2, 256>>>(verts, nd, RAW(0), RAW(1), RAW(3),
                                      dirs_l, dirs_m0, dirs_g0);
    // 2) BN stats for l, m0, g0
    stats3_kernel<<<96, 256>>>(RAW(0), g_l,  be_l,  SC(0), SH(0),
                               RAW(1), g_m0, be_m0, SC(1), SH(1),
                               RAW(3), g_g0, be_g0, SC(3), SH(3));
    // 3) fm@W for medium and global-1 in one grid
    gemm_dual_kernel<<<512, 256>>>(RAW(1), SC(1), SH(1), W_m1, b_m1, fc_m, fs_m,
                                   RAW(3), SC(3), SH(3), W_g1, b_g1, fc_g, fs_g);
    // 4) layer convs m (K=20) and g1 (K=100), warp-pair per point
    conv_dual_kernel<<<2048, 256>>>(nd, dirs_m1, fc_m, fs_m, RAW(2),
                                        dirs_g1, fc_g, fs_g, RAW(4));
    // 5) BN stats m1 + g1
    stats2_kernel<<<64, 256>>>(RAW(2), g_m1, be_m1, SC(2), SH(2),
                               RAW(4), g_g1, be_g1, SC(4), SH(4));
    // 6) global-2 fm@W
    gemm_split_kernel<<<256, 256>>>(RAW(4), SC(4), SH(4), W_g2, b_g2, fc_g, fs_g);
    // 7) global-2 layer conv (K=100)
    conv_single_kernel<<<1024, 256>>>(nd, dirs_g2, fc_g, fs_g, RAW(5));
    // 8) BN stats g2
    stats1_kernel<<<32, 256>>>(RAW(5), g_g2, be_g2, SC(5), SH(5));
    // 9) concat + down projection + relu
    gemm_final_kernel<<<256, 256>>>(RAW(0), SC(0), SH(0),
                                    RAW(2), SC(2), SH(2),
                                    RAW(5), SC(5), SH(5),
                                    W_down, b_down, out);
#undef RAW
#undef SC
#undef SH
}